// round 1
// baseline (speedup 1.0000x reference)
#include <cuda_runtime.h>
#include <math.h>

#define BB 4
#define NN 300
#define CC 80
#define MM 24
#define CF 128
#define HF 64
#define HM 224
#define TT 28

#define S_IMG 896.0f
#define CENTER_R 44.8f
#define EPSF 1e-8f

// ---------------- scratch (device globals; no allocation allowed) ----------------
__device__ float  g_proj[BB*MM*HF*HF];   // class-projected feature maps per (b, gt)
__device__ float  g_cost[BB*MM*NN];      // cost[b][j][i]
__device__ float  g_iouv[BB*MM*NN];      // valid-masked iou[b][j][i]
__device__ int    g_valid[BB*NN];
__device__ int    g_dynk[BB*MM];
__device__ int    g_gtind[BB*NN];
__device__ double g_acc[5];              // cls, l1, giou, mask, ninst

// ---------------- helpers ----------------
__device__ __forceinline__ float sigm(float x){ return 1.f/(1.f+expf(-x)); }

// IoU on raw boxes with contraction-free IEEE ops (feeds dyn_k -> must be bit-faithful)
__device__ __forceinline__ float iou_exact(float ax1,float ay1,float ax2,float ay2,
                                           float bx1,float by1,float bx2,float by2){
    float ltx=fmaxf(ax1,bx1), lty=fmaxf(ay1,by1);
    float rbx=fminf(ax2,bx2), rby=fminf(ay2,by2);
    float w=fmaxf(__fsub_rn(rbx,ltx),0.f), h=fmaxf(__fsub_rn(rby,lty),0.f);
    float inter=__fmul_rn(w,h);
    float aA=__fmul_rn(fmaxf(__fsub_rn(ax2,ax1),0.f), fmaxf(__fsub_rn(ay2,ay1),0.f));
    float aB=__fmul_rn(fmaxf(__fsub_rn(bx2,bx1),0.f), fmaxf(__fsub_rn(by2,by1),0.f));
    float uni=__fsub_rn(__fadd_rn(aA,aB), inter);
    return __fdiv_rn(inter, __fadd_rn(uni, EPSF));
}

__device__ __forceinline__ float giou_pair(float a0,float a1,float a2,float a3,
                                           float g0,float g1,float g2,float g3){
    float ltx=fmaxf(a0,g0), lty=fmaxf(a1,g1);
    float rbx=fminf(a2,g2), rby=fminf(a3,g3);
    float w=fmaxf(rbx-ltx,0.f), h=fmaxf(rby-lty,0.f);
    float inter=w*h;
    float aA=fmaxf(a2-a0,0.f)*fmaxf(a3-a1,0.f);
    float aB=fmaxf(g2-g0,0.f)*fmaxf(g3-g1,0.f);
    float uni=aA+aB-inter;
    float iou=inter/(uni+EPSF);
    float ex=fminf(a0,g0), ey=fminf(a1,g1);
    float fx=fmaxf(a2,g2), fy=fmaxf(a3,g3);
    float enc=fmaxf(fx-ex,0.f)*fmaxf(fy-ey,0.f);
    return iou-(enc-uni)/(enc+EPSF);
}

__device__ __forceinline__ float bilerp(const float* img,int W,int H,float X,float Y){
    float x0f=fminf(fmaxf(floorf(X),0.f),(float)(W-1));
    float y0f=fminf(fmaxf(floorf(Y),0.f),(float)(H-1));
    float wx=fminf(fmaxf(X-x0f,0.f),1.f);
    float wy=fminf(fmaxf(Y-y0f,0.f),1.f);
    int x0=(int)x0f, y0=(int)y0f;
    int x1=min(x0+1,W-1), y1=min(y0+1,H-1);
    float g00=img[y0*W+x0], g01=img[y0*W+x1];
    float g10=img[y1*W+x0], g11=img[y1*W+x1];
    return g00*(1.f-wx)*(1.f-wy)+g01*wx*(1.f-wy)+g10*(1.f-wx)*wy+g11*wx*wy;
}

// ---------------- kernels ----------------
__global__ void k_init(){
    for(int i=0;i<5;i++) g_acc[i]=0.0;
}

// proj[b][j][pix] = sum_f feat[b][f][pix] * w_mask[gt_cls[b][j]][f]
__global__ void k_proj(const float* __restrict__ feat, const float* __restrict__ wmask,
                       const int* __restrict__ gcls){
    __shared__ float wm[MM*CF];
    int b=blockIdx.y;
    int tid=threadIdx.x;
    for(int idx=tid; idx<MM*CF; idx+=blockDim.x){
        int j=idx/CF, f=idx%CF;
        wm[idx]=wmask[gcls[b*MM+j]*CF+f];
    }
    __syncthreads();
    int pix=blockIdx.x*blockDim.x+tid;         // 16 blocks * 256 = 4096
    float acc[MM];
    #pragma unroll
    for(int j=0;j<MM;j++) acc[j]=0.f;
    const float* fb = feat + ((size_t)b*CF)*(HF*HF) + pix;
    for(int f=0;f<CF;f++){
        float v=fb[(size_t)f*(HF*HF)];
        #pragma unroll
        for(int j=0;j<MM;j++) acc[j] += v*wm[j*CF+f];
    }
    #pragma unroll
    for(int j=0;j<MM;j++) g_proj[((b*MM+j)*(HF*HF))+pix]=acc[j];
}

__global__ void k_pairwise(const float* __restrict__ logits, const float* __restrict__ boxes,
                           const int* __restrict__ gcls, const float* __restrict__ gbox){
    int b=blockIdx.x, tid=threadIdx.x;
    __shared__ float scx[NN], scy[NN];
    __shared__ int   sval[NN];
    __shared__ float sg[MM][4];
    __shared__ float sgc[MM][2];
    __shared__ int   sgcls[MM];
    if(tid<MM){
        float x1=gbox[(b*MM+tid)*4+0], y1=gbox[(b*MM+tid)*4+1];
        float x2=gbox[(b*MM+tid)*4+2], y2=gbox[(b*MM+tid)*4+3];
        sg[tid][0]=x1; sg[tid][1]=y1; sg[tid][2]=x2; sg[tid][3]=y2;
        sgc[tid][0]=(x1+x2)*0.5f; sgc[tid][1]=(y1+y2)*0.5f;
        sgcls[tid]=gcls[b*MM+tid];
    }
    __syncthreads();
    // stage 1: proposal centers + validity
    for(int i=tid;i<NN;i+=blockDim.x){
        const float* bx=&boxes[(size_t)(b*NN+i)*4];
        float cx=(bx[0]+bx[2])*0.5f, cy=(bx[1]+bx[3])*0.5f;
        scx[i]=cx; scy[i]=cy;
        int any=0;
        for(int j=0;j<MM;j++){
            bool ingt = (cx>=sg[j][0]) && (cx<=sg[j][2]) && (cy>=sg[j][1]) && (cy<=sg[j][3]);
            bool inct = (fabsf(cx-sgc[j][0])<=CENTER_R) && (fabsf(cy-sgc[j][1])<=CENTER_R);
            any |= (ingt||inct);
        }
        sval[i]=any;
        g_valid[b*NN+i]=any;
    }
    __syncthreads();
    // stage 2: pairwise cost & masked iou
    for(int pr=tid; pr<NN*MM; pr+=blockDim.x){
        int i=pr%NN, j=pr/NN;
        const float* bx=&boxes[(size_t)(b*NN+i)*4];
        float ax1=bx[0],ay1=bx[1],ax2=bx[2],ay2=bx[3];
        float gx1=sg[j][0],gy1=sg[j][1],gx2=sg[j][2],gy2=sg[j][3];
        // focal cost at gt class
        float x=logits[(size_t)(b*NN+i)*CC + sgcls[j]];
        float p=sigm(x);
        float neg=-logf(1.f-p+EPSF)*0.75f*p*p;
        float pos=-logf(p+EPSF)*0.25f*(1.f-p)*(1.f-p);
        float cls_cost=2.f*(pos-neg);
        // normalized boxes
        float na0=ax1/S_IMG,na1=ay1/S_IMG,na2=ax2/S_IMG,na3=ay2/S_IMG;
        float ng0=gx1/S_IMG,ng1=gy1/S_IMG,ng2=gx2/S_IMG,ng3=gy2/S_IMG;
        float l1c=5.f*(fabsf(na0-ng0)+fabsf(na1-ng1)+fabsf(na2-ng2)+fabsf(na3-ng3));
        float ngiou=giou_pair(na0,na1,na2,na3,ng0,ng1,ng2,ng3);
        float cx=scx[i], cy=scy[i];
        bool ingt = (cx>=gx1)&&(cx<=gx2)&&(cy>=gy1)&&(cy<=gy2);
        bool inct = (fabsf(cx-sgc[j][0])<=CENTER_R)&&(fabsf(cy-sgc[j][1])<=CENTER_R);
        float cost=cls_cost+l1c+2.f*(1.f-ngiou);
        cost += (ingt&&inct)?0.f:1e5f;
        cost += sval[i]?0.f:1e9f;
        g_cost[(b*MM+j)*NN+i]=cost;
        float iou=iou_exact(ax1,ay1,ax2,ay2,gx1,gy1,gx2,gy2);
        g_iouv[(b*MM+j)*NN+i]= sval[i]? iou : 0.f;
    }
}

__global__ void k_dynk(){
    int b=blockIdx.x, j=threadIdx.x;
    if(j>=MM) return;
    const float* col=&g_iouv[(b*MM+j)*NN];
    float t[10];
    #pragma unroll
    for(int k=0;k<10;k++) t[k]=-1.f;
    for(int i=0;i<NN;i++){
        float v=col[i];
        if(v>t[9]){
            int k=9;
            #pragma unroll
            for(int q=9;q>0;q--){
                if(t[q-1]<v){ t[q]=t[q-1]; k=q-1; } else break;
            }
            t[k]=v;
        }
    }
    float s=0.f;
    #pragma unroll
    for(int k=0;k<10;k++) s+=t[k];   // descending order, matching top_k then sum
    int dk=(int)s;                    // trunc toward zero (s>=0)
    if(dk<1)dk=1; if(dk>NN)dk=NN;
    g_dynk[b*MM+j]=dk;
}

// warp per proposal: stable ranks + dynamic-k matching + argmin resolution
__global__ void k_assign(){
    int gw=(blockIdx.x*blockDim.x+threadIdx.x)>>5;
    int lane=threadIdx.x&31;
    if(gw>=BB*NN) return;
    int b=gw/NN, i=gw%NN;
    if(!g_valid[b*NN+i]){ if(lane==0) g_gtind[b*NN+i]=0; return; }
    float myc=(lane<MM)? g_cost[(b*MM+lane)*NN+i] : 3.4e38f;
    // argmin over j (first-index tie-break)
    float bv=myc; int bi=lane;
    #pragma unroll
    for(int off=16;off;off>>=1){
        float ov=__shfl_down_sync(0xffffffffu,bv,off);
        int   oi=__shfl_down_sync(0xffffffffu,bi,off);
        if(ov<bv || (ov==bv && oi<bi)){bv=ov;bi=oi;}
    }
    int best=__shfl_sync(0xffffffffu,bi,0);
    int cnt=0, first=-1;
    for(int j=0;j<MM;j++){
        float cij=__shfl_sync(0xffffffffu,myc,j);
        const float* col=&g_cost[(b*MM+j)*NN];
        int r=0;
        for(int k=lane;k<NN;k+=32){
            float ck=col[k];
            r += (ck<cij) || (ck==cij && k<i);
        }
        #pragma unroll
        for(int off=16;off;off>>=1) r+=__shfl_down_sync(0xffffffffu,r,off);
        r=__shfl_sync(0xffffffffu,r,0);
        if(r<g_dynk[b*MM+j]){ cnt++; if(first<0) first=j; }
    }
    int gi=(cnt>1)?best:((cnt==1)?first:best);
    if(lane==0) g_gtind[b*NN+i]=gi;
}

// focal cls loss over all [b,n,c] + matched L1/GIoU + ninst
__global__ void k_loss1(const float* __restrict__ logits, const float* __restrict__ boxes,
                        const int* __restrict__ gcls, const float* __restrict__ gbox){
    int id=blockIdx.x*blockDim.x+threadIdx.x;
    double cl=0.0, l1=0.0, gl=0.0, wv=0.0;
    if(id<BB*NN){
        int b=id/NN;
        int valid=g_valid[id];
        int j=g_gtind[id];
        int mcls=gcls[b*MM+j];
        const float* lg=&logits[(size_t)id*CC];
        for(int cc=0;cc<CC;cc++){
            float x=lg[cc];
            float l=(valid && cc==mcls)?1.f:0.f;
            float p=sigm(x);
            float ce=fmaxf(x,0.f)+log1pf(expf(-fabsf(x))) - x*l;
            float pt=p*l+(1.f-p)*(1.f-l);
            float at=0.25f*l+0.75f*(1.f-l);
            float om=1.f-pt;
            cl += (double)(at*om*om*ce);
        }
        if(valid){
            const float* bx=&boxes[(size_t)id*4];
            const float* gb=&gbox[(size_t)(b*MM+j)*4];
            float na0=bx[0]/S_IMG,na1=bx[1]/S_IMG,na2=bx[2]/S_IMG,na3=bx[3]/S_IMG;
            float ng0=gb[0]/S_IMG,ng1=gb[1]/S_IMG,ng2=gb[2]/S_IMG,ng3=gb[3]/S_IMG;
            l1=(double)(fabsf(na0-ng0)+fabsf(na1-ng1)+fabsf(na2-ng2)+fabsf(na3-ng3));
            gl=(double)(1.f-giou_pair(na0,na1,na2,na3,ng0,ng1,ng2,ng3));
            wv=1.0;
        }
    }
    #pragma unroll
    for(int off=16;off;off>>=1){
        cl+=__shfl_down_sync(0xffffffffu,cl,off);
        l1+=__shfl_down_sync(0xffffffffu,l1,off);
        gl+=__shfl_down_sync(0xffffffffu,gl,off);
        wv+=__shfl_down_sync(0xffffffffu,wv,off);
    }
    if((threadIdx.x&31)==0){
        atomicAdd(&g_acc[0],cl);
        atomicAdd(&g_acc[1],l1);
        atomicAdd(&g_acc[2],gl);
        atomicAdd(&g_acc[4],wv);
    }
}

// block per proposal: dice mask loss using precomputed projected map (1 channel)
__global__ void k_mask(const float* __restrict__ boxes, const float* __restrict__ gbox,
                       const float* __restrict__ gmask){
    int id=blockIdx.x;
    int b=id/NN, i=id%NN;
    if(!g_valid[id]) return;
    int j=g_gtind[id];
    const float* pj=&g_proj[(size_t)(b*MM+j)*(HF*HF)];
    const float* gm=&gmask[(size_t)(b*MM+j)*(HM*HM)];
    const float* bx=&boxes[(size_t)id*4];
    const float* gb=&gbox[(size_t)(b*MM+j)*4];
    const float FS=(float)(64.0/896.0);
    float px1=bx[0]*FS, py1=bx[1]*FS, px2=bx[2]*FS, py2=bx[3]*FS;
    float qx1=gb[0]*0.25f, qy1=gb[1]*0.25f, qx2=gb[2]*0.25f, qy2=gb[3]*0.25f;
    float inter=0.f, sm=0.f, sg=0.f;
    for(int pix=threadIdx.x; pix<TT*TT; pix+=blockDim.x){
        int ty=pix/TT, tx=pix%TT;
        float ux=((float)tx+0.5f)/28.f, uy=((float)ty+0.5f)/28.f;
        float X=px1+(px2-px1)*ux-0.5f, Y=py1+(py2-py1)*uy-0.5f;
        float mv=sigm(bilerp(pj,HF,HF,X,Y));
        float Xg=qx1+(qx2-qx1)*ux-0.5f, Yg=qy1+(qy2-qy1)*uy-0.5f;
        float gv=bilerp(gm,HM,HM,Xg,Yg);
        inter+=mv*gv; sm+=mv; sg+=gv;
    }
    // block reduce (256 threads = 8 warps)
    int lane=threadIdx.x&31, wid=threadIdx.x>>5;
    #pragma unroll
    for(int off=16;off;off>>=1){
        inter+=__shfl_down_sync(0xffffffffu,inter,off);
        sm   +=__shfl_down_sync(0xffffffffu,sm,off);
        sg   +=__shfl_down_sync(0xffffffffu,sg,off);
    }
    __shared__ float shI[8], shM[8], shG[8];
    if(lane==0){ shI[wid]=inter; shM[wid]=sm; shG[wid]=sg; }
    __syncthreads();
    if(threadIdx.x==0){
        float I=0.f,M=0.f,G=0.f;
        #pragma unroll
        for(int w=0;w<8;w++){ I+=shI[w]; M+=shM[w]; G+=shG[w]; }
        float term=1.f-2.f*I/(M+G+EPSF);
        atomicAdd(&g_acc[3],(double)term);
    }
}

__global__ void k_final(float* __restrict__ out){
    double ninst=g_acc[4];
    out[0]=(float)(2.0*g_acc[0]/ninst);
    out[1]=(float)(5.0*g_acc[1]/ninst);
    out[2]=(float)(2.0*g_acc[2]/ninst);
    out[3]=(float)(5.0*g_acc[3]/ninst);
}

extern "C" void kernel_launch(void* const* d_in, const int* in_sizes, int n_in,
                              void* d_out, int out_size){
    const float* logits=(const float*)d_in[0];
    const float* boxes =(const float*)d_in[1];
    const float* feat  =(const float*)d_in[2];
    const float* wmask =(const float*)d_in[3];
    const int*   gcls  =(const int*)  d_in[4];
    const float* gbox  =(const float*)d_in[5];
    const float* gmask =(const float*)d_in[6];
    float* out=(float*)d_out;

    k_init<<<1,1>>>();
    k_proj<<<dim3(16,BB),256>>>(feat,wmask,gcls);
    k_pairwise<<<BB,256>>>(logits,boxes,gcls,gbox);
    k_dynk<<<BB,32>>>();
    k_assign<<<(BB*NN*32)/256,256>>>();
    k_loss1<<<(BB*NN+255)/256,256>>>(logits,boxes,gcls,gbox);
    k_mask<<<BB*NN,256>>>(boxes,gbox,gmask);
    k_final<<<1,1>>>(out);
}

// round 2
// speedup vs baseline: 2.0516x; 2.0516x over previous
#include <cuda_runtime.h>
#include <math.h>

#define BB 4
#define NN 300
#define CC 80
#define MM 24
#define CF 128
#define HF 64
#define HM 224
#define TT 28

#define S_IMG 896.0f
#define CENTER_R 44.8f
#define EPSF 1e-8f

// ---------------- scratch (device globals) ----------------
__device__ float  g_proj[BB*MM*HF*HF];   // class-projected feature maps per (b, gt)
__device__ float  g_cost[BB*MM*NN];      // cost[b][j][i]
__device__ int    g_valid[BB*NN];
__device__ int    g_dynk[BB*MM];
__device__ unsigned g_match[BB*NN];      // bitmask over 24 gt columns
__device__ int    g_gtind[BB*NN];
__device__ double g_acc[5];              // cls, l1, giou, mask, ninst

// ---------------- helpers ----------------
__device__ __forceinline__ float sigm(float x){ return 1.f/(1.f+expf(-x)); }

// IoU on raw boxes, contraction-free IEEE (feeds dyn_k -> bit-faithful)
__device__ __forceinline__ float iou_exact(float ax1,float ay1,float ax2,float ay2,
                                           float bx1,float by1,float bx2,float by2){
    float ltx=fmaxf(ax1,bx1), lty=fmaxf(ay1,by1);
    float rbx=fminf(ax2,bx2), rby=fminf(ay2,by2);
    float w=fmaxf(__fsub_rn(rbx,ltx),0.f), h=fmaxf(__fsub_rn(rby,lty),0.f);
    float inter=__fmul_rn(w,h);
    float aA=__fmul_rn(fmaxf(__fsub_rn(ax2,ax1),0.f), fmaxf(__fsub_rn(ay2,ay1),0.f));
    float aB=__fmul_rn(fmaxf(__fsub_rn(bx2,bx1),0.f), fmaxf(__fsub_rn(by2,by1),0.f));
    float uni=__fsub_rn(__fadd_rn(aA,aB), inter);
    return __fdiv_rn(inter, __fadd_rn(uni, EPSF));
}

__device__ __forceinline__ float giou_pair(float a0,float a1,float a2,float a3,
                                           float g0,float g1,float g2,float g3){
    float ltx=fmaxf(a0,g0), lty=fmaxf(a1,g1);
    float rbx=fminf(a2,g2), rby=fminf(a3,g3);
    float w=fmaxf(rbx-ltx,0.f), h=fmaxf(rby-lty,0.f);
    float inter=w*h;
    float aA=fmaxf(a2-a0,0.f)*fmaxf(a3-a1,0.f);
    float aB=fmaxf(g2-g0,0.f)*fmaxf(g3-g1,0.f);
    float uni=aA+aB-inter;
    float iou=inter/(uni+EPSF);
    float ex=fminf(a0,g0), ey=fminf(a1,g1);
    float fx=fmaxf(a2,g2), fy=fmaxf(a3,g3);
    float enc=fmaxf(fx-ex,0.f)*fmaxf(fy-ey,0.f);
    return iou-(enc-uni)/(enc+EPSF);
}

__device__ __forceinline__ float bilerp(const float* img,int W,int H,float X,float Y){
    float x0f=fminf(fmaxf(floorf(X),0.f),(float)(W-1));
    float y0f=fminf(fmaxf(floorf(Y),0.f),(float)(H-1));
    float wx=fminf(fmaxf(X-x0f,0.f),1.f);
    float wy=fminf(fmaxf(Y-y0f,0.f),1.f);
    int x0=(int)x0f, y0=(int)y0f;
    int x1=min(x0+1,W-1), y1=min(y0+1,H-1);
    float g00=img[y0*W+x0], g01=img[y0*W+x1];
    float g10=img[y1*W+x0], g11=img[y1*W+x1];
    return g00*(1.f-wx)*(1.f-wy)+g01*wx*(1.f-wy)+g10*(1.f-wx)*wy+g11*wx*wy;
}

// ---------------- kernels ----------------

// proj[b][j][pix] = sum_f feat[b][f][pix] * w_mask[gt_cls[b][j]][f]
// also clears the accumulators (runs first in stream order)
__global__ void k_proj(const float* __restrict__ feat, const float* __restrict__ wmask,
                       const int* __restrict__ gcls){
    __shared__ float wm[MM*CF];
    int b=blockIdx.y;
    int tid=threadIdx.x;
    if(blockIdx.x==0 && b==0 && tid<5) g_acc[tid]=0.0;
    for(int idx=tid; idx<MM*CF; idx+=blockDim.x){
        int j=idx/CF, f=idx%CF;
        wm[idx]=wmask[gcls[b*MM+j]*CF+f];
    }
    __syncthreads();
    int pix=blockIdx.x*blockDim.x+tid;         // 16 blocks * 256 = 4096
    float acc[MM];
    #pragma unroll
    for(int j=0;j<MM;j++) acc[j]=0.f;
    const float* fb = feat + ((size_t)b*CF)*(HF*HF) + pix;
    for(int f=0;f<CF;f++){
        float v=fb[(size_t)f*(HF*HF)];
        #pragma unroll
        for(int j=0;j<MM;j++) acc[j] += v*wm[j*CF+f];
    }
    #pragma unroll
    for(int j=0;j<MM;j++) g_proj[((b*MM+j)*(HF*HF))+pix]=acc[j];
}

// one block per image, 768 threads = 24 warps; warp j owns GT column j.
// Computes validity, cost matrix, and dynamic-k (fused top-10) in one pass.
__global__ void k_pairwise(const float* __restrict__ logits, const float* __restrict__ boxes,
                           const int* __restrict__ gcls, const float* __restrict__ gbox){
    int b=blockIdx.x, tid=threadIdx.x;
    int wj=tid>>5, lane=tid&31;
    __shared__ float scx[NN], scy[NN];
    __shared__ int   sval[NN];
    __shared__ float sg[MM][4];
    __shared__ float sgc[MM][2];
    __shared__ int   sgcls[MM];
    if(tid<MM){
        float x1=gbox[(b*MM+tid)*4+0], y1=gbox[(b*MM+tid)*4+1];
        float x2=gbox[(b*MM+tid)*4+2], y2=gbox[(b*MM+tid)*4+3];
        sg[tid][0]=x1; sg[tid][1]=y1; sg[tid][2]=x2; sg[tid][3]=y2;
        sgc[tid][0]=(x1+x2)*0.5f; sgc[tid][1]=(y1+y2)*0.5f;
        sgcls[tid]=gcls[b*MM+tid];
    }
    __syncthreads();
    // stage 1: proposal centers + validity (+ clear match bitmask)
    for(int i=tid;i<NN;i+=blockDim.x){
        const float* bx=&boxes[(size_t)(b*NN+i)*4];
        float cx=(bx[0]+bx[2])*0.5f, cy=(bx[1]+bx[3])*0.5f;
        scx[i]=cx; scy[i]=cy;
        int any=0;
        #pragma unroll 4
        for(int j=0;j<MM;j++){
            bool ingt = (cx>=sg[j][0]) && (cx<=sg[j][2]) && (cy>=sg[j][1]) && (cy<=sg[j][3]);
            bool inct = (fabsf(cx-sgc[j][0])<=CENTER_R) && (fabsf(cy-sgc[j][1])<=CENTER_R);
            any |= (ingt||inct);
        }
        sval[i]=any;
        g_valid[b*NN+i]=any;
        g_match[b*NN+i]=0u;
    }
    __syncthreads();
    // stage 2: warp wj computes its whole column + maintains lane-local top-10 IoU
    if(wj<MM){
        int j=wj;
        float gx1=sg[j][0],gy1=sg[j][1],gx2=sg[j][2],gy2=sg[j][3];
        float gcxv=sgc[j][0], gcyv=sgc[j][1];
        int cls_j=sgcls[j];
        float ng0=gx1/S_IMG,ng1=gy1/S_IMG,ng2=gx2/S_IMG,ng3=gy2/S_IMG;
        float loc[10];
        #pragma unroll
        for(int k=0;k<10;k++) loc[k]=-1e30f;
        for(int i=lane;i<NN;i+=32){
            const float* bx=&boxes[(size_t)(b*NN+i)*4];
            float ax1=bx[0],ay1=bx[1],ax2=bx[2],ay2=bx[3];
            float x=logits[(size_t)(b*NN+i)*CC + cls_j];
            float p=sigm(x);
            float neg=-logf(1.f-p+EPSF)*0.75f*p*p;
            float pos=-logf(p+EPSF)*0.25f*(1.f-p)*(1.f-p);
            float cls_cost=2.f*(pos-neg);
            float na0=ax1/S_IMG,na1=ay1/S_IMG,na2=ax2/S_IMG,na3=ay2/S_IMG;
            float l1c=5.f*(fabsf(na0-ng0)+fabsf(na1-ng1)+fabsf(na2-ng2)+fabsf(na3-ng3));
            float ngiou=giou_pair(na0,na1,na2,na3,ng0,ng1,ng2,ng3);
            float cx=scx[i], cy=scy[i];
            bool ingt = (cx>=gx1)&&(cx<=gx2)&&(cy>=gy1)&&(cy<=gy2);
            bool inct = (fabsf(cx-gcxv)<=CENTER_R)&&(fabsf(cy-gcyv)<=CENTER_R);
            float cost=cls_cost+l1c+2.f*(1.f-ngiou);
            cost += (ingt&&inct)?0.f:1e5f;
            cost += sval[i]?0.f:1e9f;
            g_cost[(b*MM+j)*NN+i]=cost;
            float iou=iou_exact(ax1,ay1,ax2,ay2,gx1,gy1,gx2,gy2);
            float v = sval[i]? iou : 0.f;
            // lane-local sorted-descending top-10 insertion
            if(v>loc[9]){
                int k=9;
                #pragma unroll
                for(int q=9;q>0;q--){
                    if(loc[q-1]<v){ loc[q]=loc[q-1]; k=q-1; } else break;
                }
                loc[k]=v;
            }
        }
        // warp merge: 10 rounds of max-of-heads, summed in descending order
        int p=0; float s=0.f;
        #pragma unroll
        for(int r=0;r<10;r++){
            float h=(p<10)?loc[p]:-1e30f;
            float m=h;
            #pragma unroll
            for(int off=16;off;off>>=1)
                m=fmaxf(m,__shfl_xor_sync(0xffffffffu,m,off));
            s+=m;
            unsigned ball=__ballot_sync(0xffffffffu, h==m);
            int src=__ffs(ball)-1;
            if(lane==src) p++;
        }
        if(lane==0){
            int dk=(int)s;
            if(dk<1)dk=1; if(dk>NN)dk=NN;
            g_dynk[b*MM+j]=dk;
        }
    }
}

// block per (b, j): rank every proposal within column j, set match bit if rank < dyn_k
__global__ void k_rank(){
    int b=blockIdx.x/MM, j=blockIdx.x%MM;
    __shared__ float col[NN];
    int tid=threadIdx.x;
    for(int i=tid;i<NN;i+=blockDim.x) col[i]=g_cost[(b*MM+j)*NN+i];
    __syncthreads();
    int dk=g_dynk[b*MM+j];
    for(int i=tid;i<NN;i+=blockDim.x){
        float myc=col[i];
        int r=0;
        #pragma unroll 4
        for(int k=0;k<NN;k++){
            float ck=col[k];
            r += (ck<myc) || (ck==myc && k<i);
        }
        if(r<dk && g_valid[b*NN+i])
            atomicOr(&g_match[b*NN+i], 1u<<j);
    }
}

// warp per proposal: resolve assignment + focal cls + L1 + GIoU; block-reduced atomics
__global__ void k_loss1(const float* __restrict__ logits, const float* __restrict__ boxes,
                        const int* __restrict__ gcls, const float* __restrict__ gbox){
    int gw=(blockIdx.x*blockDim.x+threadIdx.x)>>5;
    int lane=threadIdx.x&31, wid=threadIdx.x>>5;
    double cl=0.0, l1=0.0, gl=0.0, wv=0.0;
    if(gw<BB*NN){
        int b=gw/NN, i=gw%NN;
        int valid=g_valid[gw];
        int gi=0;
        if(valid){
            // argmin over cost row (first-index tie-break)
            float myc=(lane<MM)? g_cost[(b*MM+lane)*NN+i] : 3.4e38f;
            float bv=myc; int bi=lane;
            #pragma unroll
            for(int off=16;off;off>>=1){
                float ov=__shfl_down_sync(0xffffffffu,bv,off);
                int   oi=__shfl_down_sync(0xffffffffu,bi,off);
                if(ov<bv || (ov==bv && oi<bi)){bv=ov;bi=oi;}
            }
            int best=__shfl_sync(0xffffffffu,bi,0);
            unsigned mbits=g_match[gw];
            int cnt=__popc(mbits);
            gi=(cnt==1)? (__ffs(mbits)-1) : best;
            g_gtind[gw]=gi;
        } else {
            if(lane==0) g_gtind[gw]=0;
        }
        int mcls=gcls[b*MM+gi];
        const float* lg=&logits[(size_t)gw*CC];
        for(int cc=lane;cc<CC;cc+=32){
            float x=lg[cc];
            float l=(valid && cc==mcls)?1.f:0.f;
            float p=sigm(x);
            float ce=fmaxf(x,0.f)+log1pf(expf(-fabsf(x))) - x*l;
            float pt=p*l+(1.f-p)*(1.f-l);
            float at=0.25f*l+0.75f*(1.f-l);
            float om=1.f-pt;
            cl += (double)(at*om*om*ce);
        }
        if(valid && lane==0){
            const float* bx=&boxes[(size_t)gw*4];
            const float* gb=&gbox[(size_t)(b*MM+gi)*4];
            float na0=bx[0]/S_IMG,na1=bx[1]/S_IMG,na2=bx[2]/S_IMG,na3=bx[3]/S_IMG;
            float ng0=gb[0]/S_IMG,ng1=gb[1]/S_IMG,ng2=gb[2]/S_IMG,ng3=gb[3]/S_IMG;
            l1=(double)(fabsf(na0-ng0)+fabsf(na1-ng1)+fabsf(na2-ng2)+fabsf(na3-ng3));
            gl=(double)(1.f-giou_pair(na0,na1,na2,na3,ng0,ng1,ng2,ng3));
            wv=1.0;
        }
    }
    // warp reduce
    #pragma unroll
    for(int off=16;off;off>>=1){
        cl+=__shfl_down_sync(0xffffffffu,cl,off);
        l1+=__shfl_down_sync(0xffffffffu,l1,off);
        gl+=__shfl_down_sync(0xffffffffu,gl,off);
        wv+=__shfl_down_sync(0xffffffffu,wv,off);
    }
    __shared__ double sh[4][8];
    if(lane==0){ sh[0][wid]=cl; sh[1][wid]=l1; sh[2][wid]=gl; sh[3][wid]=wv; }
    __syncthreads();
    if(threadIdx.x==0){
        double a=0,bb2=0,cc2=0,dd=0;
        #pragma unroll
        for(int w=0;w<8;w++){ a+=sh[0][w]; bb2+=sh[1][w]; cc2+=sh[2][w]; dd+=sh[3][w]; }
        atomicAdd(&g_acc[0],a);
        atomicAdd(&g_acc[1],bb2);
        atomicAdd(&g_acc[2],cc2);
        atomicAdd(&g_acc[4],dd);
    }
}

// block per proposal: dice mask loss using precomputed projected map (1 channel)
__global__ void k_mask(const float* __restrict__ boxes, const float* __restrict__ gbox,
                       const float* __restrict__ gmask){
    int id=blockIdx.x;
    int b=id/NN, i=id%NN;
    if(!g_valid[id]) return;
    int j=g_gtind[id];
    const float* pj=&g_proj[(size_t)(b*MM+j)*(HF*HF)];
    const float* gm=&gmask[(size_t)(b*MM+j)*(HM*HM)];
    const float* bx=&boxes[(size_t)id*4];
    const float* gb=&gbox[(size_t)(b*MM+j)*4];
    const float FS=(float)(64.0/896.0);
    float px1=bx[0]*FS, py1=bx[1]*FS, px2=bx[2]*FS, py2=bx[3]*FS;
    float qx1=gb[0]*0.25f, qy1=gb[1]*0.25f, qx2=gb[2]*0.25f, qy2=gb[3]*0.25f;
    float inter=0.f, sm=0.f, sg=0.f;
    for(int pix=threadIdx.x; pix<TT*TT; pix+=blockDim.x){
        int ty=pix/TT, tx=pix%TT;
        float ux=((float)tx+0.5f)/28.f, uy=((float)ty+0.5f)/28.f;
        float X=px1+(px2-px1)*ux-0.5f, Y=py1+(py2-py1)*uy-0.5f;
        float mv=sigm(bilerp(pj,HF,HF,X,Y));
        float Xg=qx1+(qx2-qx1)*ux-0.5f, Yg=qy1+(qy2-qy1)*uy-0.5f;
        float gv=bilerp(gm,HM,HM,Xg,Yg);
        inter+=mv*gv; sm+=mv; sg+=gv;
    }
    int lane=threadIdx.x&31, wid=threadIdx.x>>5;
    #pragma unroll
    for(int off=16;off;off>>=1){
        inter+=__shfl_down_sync(0xffffffffu,inter,off);
        sm   +=__shfl_down_sync(0xffffffffu,sm,off);
        sg   +=__shfl_down_sync(0xffffffffu,sg,off);
    }
    __shared__ float shI[8], shM[8], shG[8];
    if(lane==0){ shI[wid]=inter; shM[wid]=sm; shG[wid]=sg; }
    __syncthreads();
    if(threadIdx.x==0){
        float I=0.f,M=0.f,G=0.f;
        #pragma unroll
        for(int w=0;w<8;w++){ I+=shI[w]; M+=shM[w]; G+=shG[w]; }
        float term=1.f-2.f*I/(M+G+EPSF);
        atomicAdd(&g_acc[3],(double)term);
    }
}

__global__ void k_final(float* __restrict__ out){
    double ninst=g_acc[4];
    out[0]=(float)(2.0*g_acc[0]/ninst);
    out[1]=(float)(5.0*g_acc[1]/ninst);
    out[2]=(float)(2.0*g_acc[2]/ninst);
    out[3]=(float)(5.0*g_acc[3]/ninst);
}

extern "C" void kernel_launch(void* const* d_in, const int* in_sizes, int n_in,
                              void* d_out, int out_size){
    const float* logits=(const float*)d_in[0];
    const float* boxes =(const float*)d_in[1];
    const float* feat  =(const float*)d_in[2];
    const float* wmask =(const float*)d_in[3];
    const int*   gcls  =(const int*)  d_in[4];
    const float* gbox  =(const float*)d_in[5];
    const float* gmask =(const float*)d_in[6];
    float* out=(float*)d_out;

    k_proj<<<dim3(16,BB),256>>>(feat,wmask,gcls);
    k_pairwise<<<BB,768>>>(logits,boxes,gcls,gbox);
    k_rank<<<BB*MM,256>>>();
    k_loss1<<<(BB*NN*32+255)/256,256>>>(logits,boxes,gcls,gbox);
    k_mask<<<BB*NN,256>>>(boxes,gbox,gmask);
    k_final<<<1,1>>>(out);
}

// round 3
// speedup vs baseline: 2.9279x; 1.4272x over previous
#include <cuda_runtime.h>
#include <math.h>

#define BB 4
#define NN 300
#define CC 80
#define MM 24
#define CF 128
#define HF 64
#define HM 224
#define TT 28

#define S_IMG 896.0f
#define CENTER_R 44.8f
#define EPSF 1e-8f

// K1 block roles
#define PROJ_BLKS   64            // 16 per image
#define COL_BLKS    (BB*MM)       // 96
#define NEG_BLKS    75            // 75*256*5 = 96000 = BB*NN*CC
#define K1_GRID     (PROJ_BLKS+COL_BLKS+NEG_BLKS)

// ---------------- scratch (device globals) ----------------
__device__ float  g_proj[BB*MM*HF*HF];
__device__ float  g_cost[BB*MM*NN];
__device__ int    g_valid[BB*NN];
__device__ unsigned char g_matchb[BB*MM*NN];
__device__ int    g_gtind[BB*NN];
__device__ double g_acc[5] = {0,0,0,0,0};   // cls, l1, giou, mask, ninst
__device__ int    g_done = 0;

// ---------------- helpers ----------------
__device__ __forceinline__ float sigm(float x){ return 1.f/(1.f+expf(-x)); }

// IoU on raw boxes, contraction-free IEEE (feeds dyn_k -> bit-faithful)
__device__ __forceinline__ float iou_exact(float ax1,float ay1,float ax2,float ay2,
                                           float bx1,float by1,float bx2,float by2){
    float ltx=fmaxf(ax1,bx1), lty=fmaxf(ay1,by1);
    float rbx=fminf(ax2,bx2), rby=fminf(ay2,by2);
    float w=fmaxf(__fsub_rn(rbx,ltx),0.f), h=fmaxf(__fsub_rn(rby,lty),0.f);
    float inter=__fmul_rn(w,h);
    float aA=__fmul_rn(fmaxf(__fsub_rn(ax2,ax1),0.f), fmaxf(__fsub_rn(ay2,ay1),0.f));
    float aB=__fmul_rn(fmaxf(__fsub_rn(bx2,bx1),0.f), fmaxf(__fsub_rn(by2,by1),0.f));
    float uni=__fsub_rn(__fadd_rn(aA,aB), inter);
    return __fdiv_rn(inter, __fadd_rn(uni, EPSF));
}

__device__ __forceinline__ float giou_pair(float a0,float a1,float a2,float a3,
                                           float g0,float g1,float g2,float g3){
    float ltx=fmaxf(a0,g0), lty=fmaxf(a1,g1);
    float rbx=fminf(a2,g2), rby=fminf(a3,g3);
    float w=fmaxf(rbx-ltx,0.f), h=fmaxf(rby-lty,0.f);
    float inter=w*h;
    float aA=fmaxf(a2-a0,0.f)*fmaxf(a3-a1,0.f);
    float aB=fmaxf(g2-g0,0.f)*fmaxf(g3-g1,0.f);
    float uni=aA+aB-inter;
    float iou=inter/(uni+EPSF);
    float ex=fminf(a0,g0), ey=fminf(a1,g1);
    float fx=fmaxf(a2,g2), fy=fmaxf(a3,g3);
    float enc=fmaxf(fx-ex,0.f)*fmaxf(fy-ey,0.f);
    return iou-(enc-uni)/(enc+EPSF);
}

__device__ __forceinline__ float bilerp(const float* img,int W,int H,float X,float Y){
    float x0f=fminf(fmaxf(floorf(X),0.f),(float)(W-1));
    float y0f=fminf(fmaxf(floorf(Y),0.f),(float)(H-1));
    float wx=fminf(fmaxf(X-x0f,0.f),1.f);
    float wy=fminf(fmaxf(Y-y0f,0.f),1.f);
    int x0=(int)x0f, y0=(int)y0f;
    int x1=min(x0+1,W-1), y1=min(y0+1,H-1);
    float g00=img[y0*W+x0], g01=img[y0*W+x1];
    float g10=img[y1*W+x0], g11=img[y1*W+x1];
    return g00*(1.f-wx)*(1.f-wy)+g01*wx*(1.f-wy)+g10*(1.f-wx)*wy+g11*wx*wy;
}

// ================= K1: proj || cost-column+dynk+rank || negative focal =================
__global__ void k_stage1(const float* __restrict__ logits, const float* __restrict__ boxes,
                         const float* __restrict__ feat,   const float* __restrict__ wmask,
                         const int*   __restrict__ gcls,   const float* __restrict__ gbox){
    int blk=blockIdx.x, tid=threadIdx.x;
    int lane=tid&31, warp=tid>>5;

    if(blk < PROJ_BLKS){
        // ---- projected class maps ----
        __shared__ float wm[MM*CF];
        int b=blk/16;
        for(int idx=tid; idx<MM*CF; idx+=256){
            int j=idx/CF, f=idx%CF;
            wm[idx]=wmask[gcls[b*MM+j]*CF+f];
        }
        __syncthreads();
        int pix=(blk%16)*256+tid;
        float acc[MM];
        #pragma unroll
        for(int j=0;j<MM;j++) acc[j]=0.f;
        const float* fb = feat + ((size_t)b*CF)*(HF*HF) + pix;
        for(int f=0;f<CF;f++){
            float v=fb[(size_t)f*(HF*HF)];
            #pragma unroll
            for(int j=0;j<MM;j++) acc[j] += v*wm[j*CF+f];
        }
        #pragma unroll
        for(int j=0;j<MM;j++) g_proj[((b*MM+j)*(HF*HF))+pix]=acc[j];
        return;
    }

    if(blk < PROJ_BLKS+COL_BLKS){
        // ---- one cost column: cost + validity + top-10 dyn_k + rank ----
        int idx=blk-PROJ_BLKS;
        int b=idx/MM, j=idx%MM;
        __shared__ float col[NN];
        __shared__ unsigned char sval[NN];
        __shared__ float sg[MM][4];
        __shared__ float wtop[8][10];
        __shared__ int   s_dk;
        if(tid<MM){
            sg[tid][0]=gbox[(b*MM+tid)*4+0]; sg[tid][1]=gbox[(b*MM+tid)*4+1];
            sg[tid][2]=gbox[(b*MM+tid)*4+2]; sg[tid][3]=gbox[(b*MM+tid)*4+3];
        }
        __syncthreads();
        float gx1=sg[j][0],gy1=sg[j][1],gx2=sg[j][2],gy2=sg[j][3];
        float gcx=(gx1+gx2)*0.5f, gcy=(gy1+gy2)*0.5f;
        int cls_j=gcls[b*MM+j];
        float ng0=gx1/S_IMG,ng1=gy1/S_IMG,ng2=gx2/S_IMG,ng3=gy2/S_IMG;
        float loc[10];
        #pragma unroll
        for(int k=0;k<10;k++) loc[k]=-1e30f;
        for(int i=tid;i<NN;i+=256){
            const float* bx=&boxes[(size_t)(b*NN+i)*4];
            float ax1=bx[0],ay1=bx[1],ax2=bx[2],ay2=bx[3];
            float cx=(ax1+ax2)*0.5f, cy=(ay1+ay2)*0.5f;
            // validity over all 24 gt
            int any=0;
            #pragma unroll 4
            for(int q=0;q<MM;q++){
                float qx1=sg[q][0],qy1=sg[q][1],qx2=sg[q][2],qy2=sg[q][3];
                bool igt=(cx>=qx1)&&(cx<=qx2)&&(cy>=qy1)&&(cy<=qy2);
                bool ict=(fabsf(cx-(qx1+qx2)*0.5f)<=CENTER_R)&&(fabsf(cy-(qy1+qy2)*0.5f)<=CENTER_R);
                any |= (igt||ict);
            }
            sval[i]=(unsigned char)any;
            g_valid[b*NN+i]=any;
            // focal cost at gt class (precise math; feeds discrete decisions)
            float x=logits[(size_t)(b*NN+i)*CC + cls_j];
            float p=sigm(x);
            float neg=-logf(1.f-p+EPSF)*0.75f*p*p;
            float pos=-logf(p+EPSF)*0.25f*(1.f-p)*(1.f-p);
            float cls_cost=2.f*(pos-neg);
            float na0=ax1/S_IMG,na1=ay1/S_IMG,na2=ax2/S_IMG,na3=ay2/S_IMG;
            float l1c=5.f*(fabsf(na0-ng0)+fabsf(na1-ng1)+fabsf(na2-ng2)+fabsf(na3-ng3));
            float ngiou=giou_pair(na0,na1,na2,na3,ng0,ng1,ng2,ng3);
            bool ingt=(cx>=gx1)&&(cx<=gx2)&&(cy>=gy1)&&(cy<=gy2);
            bool inct=(fabsf(cx-gcx)<=CENTER_R)&&(fabsf(cy-gcy)<=CENTER_R);
            float cost=cls_cost+l1c+2.f*(1.f-ngiou);
            cost += (ingt&&inct)?0.f:1e5f;
            cost += any?0.f:1e9f;
            col[i]=cost;
            g_cost[(b*MM+j)*NN+i]=cost;
            float iou=iou_exact(ax1,ay1,ax2,ay2,gx1,gy1,gx2,gy2);
            float v=any? iou : 0.f;
            if(v>loc[9]){
                int k=9;
                #pragma unroll
                for(int q=9;q>0;q--){
                    if(loc[q-1]<v){ loc[q]=loc[q-1]; k=q-1; } else break;
                }
                loc[k]=v;
            }
        }
        // warp top-10 merge (each lane has sorted-desc loc); all lanes record maxima
        {
            int p=0; float out10[10];
            #pragma unroll
            for(int r=0;r<10;r++){
                float h=(p<10)?loc[p]:-1e30f;
                float m=h;
                #pragma unroll
                for(int off=16;off;off>>=1)
                    m=fmaxf(m,__shfl_xor_sync(0xffffffffu,m,off));
                out10[r]=m;
                unsigned ball=__ballot_sync(0xffffffffu, h==m);
                if(lane==(__ffs(ball)-1)) p++;
            }
            if(lane==0){
                #pragma unroll
                for(int r=0;r<10;r++) wtop[warp][r]=out10[r];
            }
        }
        __syncthreads();
        if(warp==0){
            int p=0; float s=0.f;
            #pragma unroll
            for(int r=0;r<10;r++){
                float h=(lane<8 && p<10)? wtop[lane][p] : -1e30f;
                float m=h;
                #pragma unroll
                for(int off=16;off;off>>=1)
                    m=fmaxf(m,__shfl_xor_sync(0xffffffffu,m,off));
                s+=m;
                unsigned ball=__ballot_sync(0xffffffffu, h==m && lane<8);
                if(lane==(__ffs(ball)-1)) p++;
            }
            if(lane==0){
                int dk=(int)s;
                if(dk<1)dk=1; if(dk>NN)dk=NN;
                s_dk=dk;
            }
        }
        __syncthreads();
        int dk=s_dk;
        // rank within the column; write match bytes (block owns its column)
        for(int i=tid;i<NN;i+=256){
            float myc=col[i];
            int r=0;
            #pragma unroll 4
            for(int k=0;k<NN;k++){
                float ck=col[k];
                r += (ck<myc) || (ck==myc && k<i);
            }
            g_matchb[(b*MM+j)*NN+i]=(unsigned char)((r<dk) && sval[i]);
        }
        return;
    }

    // ---- negative-class focal bulk: label=0 term over all (b,i,c) ----
    {
        int base=(blk-PROJ_BLKS-COL_BLKS)*1280 + tid;
        double cl=0.0;
        #pragma unroll
        for(int k=0;k<5;k++){
            int e=base+k*256;            // e < 96000 by construction
            float x=logits[e];
            float p=1.f/(1.f+__expf(-x));
            float sp=fmaxf(x,0.f)+log1pf(__expf(-fabsf(x)));
            cl += (double)(0.75f*p*p*sp);
        }
        #pragma unroll
        for(int off=16;off;off>>=1) cl+=__shfl_down_sync(0xffffffffu,cl,off);
        __shared__ double sred[8];
        if(lane==0) sred[warp]=cl;
        __syncthreads();
        if(tid==0){
            double a=0;
            #pragma unroll
            for(int w=0;w<8;w++) a+=sred[w];
            atomicAdd(&g_acc[0],a);
        }
        return;
    }
}

// ================= K2: assignment + L1/GIoU/ninst + cls correction =================
__global__ void k_assign(const float* __restrict__ logits, const float* __restrict__ boxes,
                         const int* __restrict__ gcls, const float* __restrict__ gbox){
    int b=blockIdx.x, tid=threadIdx.x;
    int lane=tid&31, warp=tid>>5;
    double corr=0.0, l1=0.0, gl=0.0, wv=0.0;
    for(int i=tid;i<NN;i+=256){
        int valid=g_valid[b*NN+i];
        // argmin over rows (first-index tie-break) + matched bits
        float bv=3.4e38f; int bi=0, cnt=0, first=-1;
        #pragma unroll 4
        for(int j=0;j<MM;j++){
            float c=g_cost[(b*MM+j)*NN+i];
            if(c<bv){bv=c;bi=j;}
            int mb=g_matchb[(b*MM+j)*NN+i];
            cnt+=mb;
            if(mb && first<0) first=j;
        }
        int gi=valid? ((cnt==1)? first : bi) : 0;
        g_gtind[b*NN+i]=gi;
        if(valid){
            const float* bx=&boxes[(size_t)(b*NN+i)*4];
            const float* gb=&gbox[(size_t)(b*MM+gi)*4];
            float na0=bx[0]/S_IMG,na1=bx[1]/S_IMG,na2=bx[2]/S_IMG,na3=bx[3]/S_IMG;
            float ng0=gb[0]/S_IMG,ng1=gb[1]/S_IMG,ng2=gb[2]/S_IMG,ng3=gb[3]/S_IMG;
            l1+=(double)(fabsf(na0-ng0)+fabsf(na1-ng1)+fabsf(na2-ng2)+fabsf(na3-ng3));
            gl+=(double)(1.f-giou_pair(na0,na1,na2,na3,ng0,ng1,ng2,ng3));
            wv+=1.0;
            // cls correction at matched class: pos - neg (label=1 term minus label=0 term)
            int mcls=gcls[b*MM+gi];
            float x=logits[(size_t)(b*NN+i)*CC+mcls];
            float p=1.f/(1.f+expf(-x));
            float sp=fmaxf(x,0.f)+log1pf(expf(-fabsf(x)));
            float posv=0.25f*(1.f-p)*(1.f-p)*(sp-x);
            float negv=0.75f*p*p*sp;
            corr += (double)(posv-negv);
        }
    }
    #pragma unroll
    for(int off=16;off;off>>=1){
        corr+=__shfl_down_sync(0xffffffffu,corr,off);
        l1  +=__shfl_down_sync(0xffffffffu,l1,off);
        gl  +=__shfl_down_sync(0xffffffffu,gl,off);
        wv  +=__shfl_down_sync(0xffffffffu,wv,off);
    }
    __shared__ double sh[4][8];
    if(lane==0){ sh[0][warp]=corr; sh[1][warp]=l1; sh[2][warp]=gl; sh[3][warp]=wv; }
    __syncthreads();
    if(tid==0){
        double a=0,b2=0,c2=0,d2=0;
        #pragma unroll
        for(int w=0;w<8;w++){ a+=sh[0][w]; b2+=sh[1][w]; c2+=sh[2][w]; d2+=sh[3][w]; }
        atomicAdd(&g_acc[0],a);
        atomicAdd(&g_acc[1],b2);
        atomicAdd(&g_acc[2],c2);
        atomicAdd(&g_acc[4],d2);
    }
}

// ================= K3: mask dice + fused finalize (last-block ticket) =================
__global__ void k_mask(const float* __restrict__ boxes, const float* __restrict__ gbox,
                       const float* __restrict__ gmask, float* __restrict__ out){
    int id=blockIdx.x;
    int b=id/NN;
    int lane=threadIdx.x&31, warp=threadIdx.x>>5;
    if(g_valid[id]){
        int j=g_gtind[id];
        const float* pj=&g_proj[(size_t)(b*MM+j)*(HF*HF)];
        const float* gm=&gmask[(size_t)(b*MM+j)*(HM*HM)];
        const float* bx=&boxes[(size_t)id*4];
        const float* gb=&gbox[(size_t)(b*MM+j)*4];
        const float FS=(float)(64.0/896.0);
        float px1=bx[0]*FS, py1=bx[1]*FS, px2=bx[2]*FS, py2=bx[3]*FS;
        float qx1=gb[0]*0.25f, qy1=gb[1]*0.25f, qx2=gb[2]*0.25f, qy2=gb[3]*0.25f;
        float inter=0.f, sm=0.f, sg=0.f;
        for(int pix=threadIdx.x; pix<TT*TT; pix+=256){
            int ty=pix/TT, tx=pix%TT;
            float ux=((float)tx+0.5f)/28.f, uy=((float)ty+0.5f)/28.f;
            float X=px1+(px2-px1)*ux-0.5f, Y=py1+(py2-py1)*uy-0.5f;
            float z=bilerp(pj,HF,HF,X,Y);
            float mv=1.f/(1.f+__expf(-z));
            float Xg=qx1+(qx2-qx1)*ux-0.5f, Yg=qy1+(qy2-qy1)*uy-0.5f;
            float gv=bilerp(gm,HM,HM,Xg,Yg);
            inter+=mv*gv; sm+=mv; sg+=gv;
        }
        #pragma unroll
        for(int off=16;off;off>>=1){
            inter+=__shfl_down_sync(0xffffffffu,inter,off);
            sm   +=__shfl_down_sync(0xffffffffu,sm,off);
            sg   +=__shfl_down_sync(0xffffffffu,sg,off);
        }
        __shared__ float shI[8], shM[8], shG[8];
        if(lane==0){ shI[warp]=inter; shM[warp]=sm; shG[warp]=sg; }
        __syncthreads();
        if(threadIdx.x==0){
            float I=0.f,M=0.f,G=0.f;
            #pragma unroll
            for(int w=0;w<8;w++){ I+=shI[w]; M+=shM[w]; G+=shG[w]; }
            atomicAdd(&g_acc[3],(double)(1.f-2.f*I/(M+G+EPSF)));
        }
    }
    // ---- ticket: last finished block finalizes + resets accumulators ----
    __shared__ int amlast;
    __threadfence();
    if(threadIdx.x==0){
        int t=atomicAdd(&g_done,1);
        amlast=(t==(int)gridDim.x-1);
    }
    __syncthreads();
    if(amlast && threadIdx.x==0){
        __threadfence();
        double ninst=g_acc[4];
        out[0]=(float)(2.0*g_acc[0]/ninst);
        out[1]=(float)(5.0*g_acc[1]/ninst);
        out[2]=(float)(2.0*g_acc[2]/ninst);
        out[3]=(float)(5.0*g_acc[3]/ninst);
        g_acc[0]=0.0; g_acc[1]=0.0; g_acc[2]=0.0; g_acc[3]=0.0; g_acc[4]=0.0;
        g_done=0;
    }
}

extern "C" void kernel_launch(void* const* d_in, const int* in_sizes, int n_in,
                              void* d_out, int out_size){
    const float* logits=(const float*)d_in[0];
    const float* boxes =(const float*)d_in[1];
    const float* feat  =(const float*)d_in[2];
    const float* wmask =(const float*)d_in[3];
    const int*   gcls  =(const int*)  d_in[4];
    const float* gbox  =(const float*)d_in[5];
    const float* gmask =(const float*)d_in[6];
    float* out=(float*)d_out;

    k_stage1<<<K1_GRID,256>>>(logits,boxes,feat,wmask,gcls,gbox);
    k_assign<<<BB,256>>>(logits,boxes,gcls,gbox);
    k_mask<<<BB*NN,256>>>(boxes,gbox,gmask,out);
}

// round 4
// speedup vs baseline: 3.0027x; 1.0255x over previous
#include <cuda_runtime.h>
#include <math.h>

#define BB 4
#define NN 300
#define CC 80
#define MM 24
#define CF 128
#define HF 64
#define HM 224
#define TT 28

#define S_IMG 896.0f
#define CENTER_R 44.8f
#define EPSF 1e-8f

// K1 roles: proj (64) || cost columns (96)
#define PROJ_BLKS   64
#define COL_BLKS    (BB*MM)
#define K1_GRID     (PROJ_BLKS+COL_BLKS)
// K2 roles: per-proposal (1200) || negative focal bulk (75)
#define PROP_BLKS   (BB*NN)
#define NEG_BLKS    75
#define K2_GRID     (PROP_BLKS+NEG_BLKS)

// ---------------- scratch (device globals) ----------------
__device__ float  g_proj[BB*MM*HF*HF];
__device__ float  g_costT[BB*NN*MM];          // transposed: [b][i][j]
__device__ unsigned char g_matchT[BB*NN*MM];  // transposed match bytes
__device__ int    g_valid[BB*NN];
__device__ double g_accb[32][5];              // banked: cls, l1, giou, mask, ninst
__device__ int    g_done = 0;

// ---------------- helpers ----------------
__device__ __forceinline__ float sigm(float x){ return 1.f/(1.f+expf(-x)); }

// IoU on raw boxes, contraction-free IEEE (feeds dyn_k -> bit-faithful)
__device__ __forceinline__ float iou_exact(float ax1,float ay1,float ax2,float ay2,
                                           float bx1,float by1,float bx2,float by2){
    float ltx=fmaxf(ax1,bx1), lty=fmaxf(ay1,by1);
    float rbx=fminf(ax2,bx2), rby=fminf(ay2,by2);
    float w=fmaxf(__fsub_rn(rbx,ltx),0.f), h=fmaxf(__fsub_rn(rby,lty),0.f);
    float inter=__fmul_rn(w,h);
    float aA=__fmul_rn(fmaxf(__fsub_rn(ax2,ax1),0.f), fmaxf(__fsub_rn(ay2,ay1),0.f));
    float aB=__fmul_rn(fmaxf(__fsub_rn(bx2,bx1),0.f), fmaxf(__fsub_rn(by2,by1),0.f));
    float uni=__fsub_rn(__fadd_rn(aA,aB), inter);
    return __fdiv_rn(inter, __fadd_rn(uni, EPSF));
}

__device__ __forceinline__ float giou_pair(float a0,float a1,float a2,float a3,
                                           float g0,float g1,float g2,float g3){
    float ltx=fmaxf(a0,g0), lty=fmaxf(a1,g1);
    float rbx=fminf(a2,g2), rby=fminf(a3,g3);
    float w=fmaxf(rbx-ltx,0.f), h=fmaxf(rby-lty,0.f);
    float inter=w*h;
    float aA=fmaxf(a2-a0,0.f)*fmaxf(a3-a1,0.f);
    float aB=fmaxf(g2-g0,0.f)*fmaxf(g3-g1,0.f);
    float uni=aA+aB-inter;
    float iou=inter/(uni+EPSF);
    float ex=fminf(a0,g0), ey=fminf(a1,g1);
    float fx=fmaxf(a2,g2), fy=fmaxf(a3,g3);
    float enc=fmaxf(fx-ex,0.f)*fmaxf(fy-ey,0.f);
    return iou-(enc-uni)/(enc+EPSF);
}

__device__ __forceinline__ float bilerp(const float* img,int W,int H,float X,float Y){
    float x0f=fminf(fmaxf(floorf(X),0.f),(float)(W-1));
    float y0f=fminf(fmaxf(floorf(Y),0.f),(float)(H-1));
    float wx=fminf(fmaxf(X-x0f,0.f),1.f);
    float wy=fminf(fmaxf(Y-y0f,0.f),1.f);
    int x0=(int)x0f, y0=(int)y0f;
    int x1=min(x0+1,W-1), y1=min(y0+1,H-1);
    float g00=img[y0*W+x0], g01=img[y0*W+x1];
    float g10=img[y1*W+x0], g11=img[y1*W+x1];
    return g00*(1.f-wx)*(1.f-wy)+g01*wx*(1.f-wy)+g10*(1.f-wx)*wy+g11*wx*wy;
}

// ================= K1: proj || cost-column+dynk+rank =================
__global__ void k_stage1(const float* __restrict__ logits, const float* __restrict__ boxes,
                         const float* __restrict__ feat,   const float* __restrict__ wmask,
                         const int*   __restrict__ gcls,   const float* __restrict__ gbox){
    int blk=blockIdx.x, tid=threadIdx.x;
    int lane=tid&31, warp=tid>>5;

    if(blk < PROJ_BLKS){
        // block 0 zeros the accumulator banks (consumed only in K2)
        if(blk==0 && tid<160) ((double*)g_accb)[tid]=0.0;
        __shared__ float wm[MM*CF];
        int b=blk/16;
        for(int idx=tid; idx<MM*CF; idx+=256){
            int j=idx/CF, f=idx%CF;
            wm[idx]=wmask[gcls[b*MM+j]*CF+f];
        }
        __syncthreads();
        int pix=(blk%16)*256+tid;
        float acc[MM];
        #pragma unroll
        for(int j=0;j<MM;j++) acc[j]=0.f;
        const float* fb = feat + ((size_t)b*CF)*(HF*HF) + pix;
        for(int f=0;f<CF;f++){
            float v=fb[(size_t)f*(HF*HF)];
            #pragma unroll
            for(int j=0;j<MM;j++) acc[j] += v*wm[j*CF+f];
        }
        #pragma unroll
        for(int j=0;j<MM;j++) g_proj[((b*MM+j)*(HF*HF))+pix]=acc[j];
        return;
    }

    // ---- one cost column: cost + validity + top-10 dyn_k + rank ----
    {
        int idx=blk-PROJ_BLKS;
        int b=idx/MM, j=idx%MM;
        __shared__ float col[NN];
        __shared__ unsigned char sval[NN];
        __shared__ float sg[MM][4];
        __shared__ float wtop[8][10];
        __shared__ int   s_dk;
        if(tid<MM){
            sg[tid][0]=gbox[(b*MM+tid)*4+0]; sg[tid][1]=gbox[(b*MM+tid)*4+1];
            sg[tid][2]=gbox[(b*MM+tid)*4+2]; sg[tid][3]=gbox[(b*MM+tid)*4+3];
        }
        __syncthreads();
        float gx1=sg[j][0],gy1=sg[j][1],gx2=sg[j][2],gy2=sg[j][3];
        float gcx=(gx1+gx2)*0.5f, gcy=(gy1+gy2)*0.5f;
        int cls_j=gcls[b*MM+j];
        float ng0=gx1/S_IMG,ng1=gy1/S_IMG,ng2=gx2/S_IMG,ng3=gy2/S_IMG;
        float loc[10];
        #pragma unroll
        for(int k=0;k<10;k++) loc[k]=-1e30f;
        for(int i=tid;i<NN;i+=256){
            const float* bx=&boxes[(size_t)(b*NN+i)*4];
            float ax1=bx[0],ay1=bx[1],ax2=bx[2],ay2=bx[3];
            float cx=(ax1+ax2)*0.5f, cy=(ay1+ay2)*0.5f;
            int any=0;
            #pragma unroll 4
            for(int q=0;q<MM;q++){
                float qx1=sg[q][0],qy1=sg[q][1],qx2=sg[q][2],qy2=sg[q][3];
                bool igt=(cx>=qx1)&&(cx<=qx2)&&(cy>=qy1)&&(cy<=qy2);
                bool ict=(fabsf(cx-(qx1+qx2)*0.5f)<=CENTER_R)&&(fabsf(cy-(qy1+qy2)*0.5f)<=CENTER_R);
                any |= (igt||ict);
            }
            sval[i]=(unsigned char)any;
            g_valid[b*NN+i]=any;
            float x=logits[(size_t)(b*NN+i)*CC + cls_j];
            float p=sigm(x);
            float neg=-logf(1.f-p+EPSF)*0.75f*p*p;
            float pos=-logf(p+EPSF)*0.25f*(1.f-p)*(1.f-p);
            float cls_cost=2.f*(pos-neg);
            float na0=ax1/S_IMG,na1=ay1/S_IMG,na2=ax2/S_IMG,na3=ay2/S_IMG;
            float l1c=5.f*(fabsf(na0-ng0)+fabsf(na1-ng1)+fabsf(na2-ng2)+fabsf(na3-ng3));
            float ngiou=giou_pair(na0,na1,na2,na3,ng0,ng1,ng2,ng3);
            bool ingt=(cx>=gx1)&&(cx<=gx2)&&(cy>=gy1)&&(cy<=gy2);
            bool inct=(fabsf(cx-gcx)<=CENTER_R)&&(fabsf(cy-gcy)<=CENTER_R);
            float cost=cls_cost+l1c+2.f*(1.f-ngiou);
            cost += (ingt&&inct)?0.f:1e5f;
            cost += any?0.f:1e9f;
            col[i]=cost;
            g_costT[(size_t)(b*NN+i)*MM+j]=cost;
            float iou=iou_exact(ax1,ay1,ax2,ay2,gx1,gy1,gx2,gy2);
            float v=any? iou : 0.f;
            if(v>loc[9]){
                int k=9;
                #pragma unroll
                for(int q=9;q>0;q--){
                    if(loc[q-1]<v){ loc[q]=loc[q-1]; k=q-1; } else break;
                }
                loc[k]=v;
            }
        }
        // warp top-10 merge
        {
            int p=0; float out10[10];
            #pragma unroll
            for(int r=0;r<10;r++){
                float h=(p<10)?loc[p]:-1e30f;
                float m=h;
                #pragma unroll
                for(int off=16;off;off>>=1)
                    m=fmaxf(m,__shfl_xor_sync(0xffffffffu,m,off));
                out10[r]=m;
                unsigned ball=__ballot_sync(0xffffffffu, h==m);
                if(lane==(__ffs(ball)-1)) p++;
            }
            if(lane==0){
                #pragma unroll
                for(int r=0;r<10;r++) wtop[warp][r]=out10[r];
            }
        }
        __syncthreads();
        if(warp==0){
            int p=0; float s=0.f;
            #pragma unroll
            for(int r=0;r<10;r++){
                float h=(lane<8 && p<10)? wtop[lane][p] : -1e30f;
                float m=h;
                #pragma unroll
                for(int off=16;off;off>>=1)
                    m=fmaxf(m,__shfl_xor_sync(0xffffffffu,m,off));
                s+=m;
                unsigned ball=__ballot_sync(0xffffffffu, h==m && lane<8);
                if(lane==(__ffs(ball)-1)) p++;
            }
            if(lane==0){
                int dk=(int)s;
                if(dk<1)dk=1; if(dk>NN)dk=NN;
                s_dk=dk;
            }
        }
        __syncthreads();
        int dk=s_dk;
        for(int i=tid;i<NN;i+=256){
            float myc=col[i];
            int r=0;
            #pragma unroll 4
            for(int k=0;k<NN;k++){
                float ck=col[k];
                r += (ck<myc) || (ck==myc && k<i);
            }
            g_matchT[(size_t)(b*NN+i)*MM+j]=(unsigned char)((r<dk) && sval[i]);
        }
    }
}

// ================= K2: per-proposal (assign + losses + mask) || neg focal; ticket finalize =================
__global__ void k_stage2(const float* __restrict__ logits, const float* __restrict__ boxes,
                         const int* __restrict__ gcls, const float* __restrict__ gbox,
                         const float* __restrict__ gmask, float* __restrict__ out){
    int blk=blockIdx.x, tid=threadIdx.x;
    int lane=tid&31, warp=tid>>5;
    int bank=blk&31;

    if(blk < PROP_BLKS){
        int id=blk, b=id/NN, i=id%NN;
        if(g_valid[id]){
            __shared__ int s_gi;
            if(warp==0){
                // inline assignment: lanes 0..23 hold (cost, match) for this proposal
                float c=(lane<MM)? g_costT[(size_t)id*MM+lane] : 3.4e38f;
                unsigned char mb=(lane<MM)? g_matchT[(size_t)id*MM+lane] : 0;
                unsigned bits=__ballot_sync(0xffffffffu, lane<MM && mb);
                float bv=c; int bi=lane;
                #pragma unroll
                for(int off=16;off;off>>=1){
                    float ov=__shfl_down_sync(0xffffffffu,bv,off);
                    int   oi=__shfl_down_sync(0xffffffffu,bi,off);
                    if(ov<bv || (ov==bv && oi<bi)){bv=ov;bi=oi;}
                }
                int best=__shfl_sync(0xffffffffu,bi,0);
                int cnt=__popc(bits);
                if(lane==0) s_gi=(cnt==1)? (__ffs(bits)-1) : best;
            }
            __syncthreads();
            int j=s_gi;
            const float* pj=&g_proj[(size_t)(b*MM+j)*(HF*HF)];
            const float* gm=&gmask[(size_t)(b*MM+j)*(HM*HM)];
            const float* bx=&boxes[(size_t)id*4];
            const float* gb=&gbox[(size_t)(b*MM+j)*4];
            const float FS=(float)(64.0/896.0);
            float px1=bx[0]*FS, py1=bx[1]*FS, px2=bx[2]*FS, py2=bx[3]*FS;
            float qx1=gb[0]*0.25f, qy1=gb[1]*0.25f, qx2=gb[2]*0.25f, qy2=gb[3]*0.25f;
            float inter=0.f, sm=0.f, sg=0.f;
            for(int pix=tid; pix<TT*TT; pix+=256){
                int ty=pix/TT, tx=pix%TT;
                float ux=((float)tx+0.5f)/28.f, uy=((float)ty+0.5f)/28.f;
                float X=px1+(px2-px1)*ux-0.5f, Y=py1+(py2-py1)*uy-0.5f;
                float z=bilerp(pj,HF,HF,X,Y);
                float mv=1.f/(1.f+__expf(-z));
                float Xg=qx1+(qx2-qx1)*ux-0.5f, Yg=qy1+(qy2-qy1)*uy-0.5f;
                float gv=bilerp(gm,HM,HM,Xg,Yg);
                inter+=mv*gv; sm+=mv; sg+=gv;
            }
            #pragma unroll
            for(int off=16;off;off>>=1){
                inter+=__shfl_down_sync(0xffffffffu,inter,off);
                sm   +=__shfl_down_sync(0xffffffffu,sm,off);
                sg   +=__shfl_down_sync(0xffffffffu,sg,off);
            }
            __shared__ float shI[8], shM[8], shG[8];
            if(lane==0){ shI[warp]=inter; shM[warp]=sm; shG[warp]=sg; }
            __syncthreads();
            if(tid==0){
                float I=0.f,M=0.f,G=0.f;
                #pragma unroll
                for(int w=0;w<8;w++){ I+=shI[w]; M+=shM[w]; G+=shG[w]; }
                double dice=(double)(1.f-2.f*I/(M+G+EPSF));
                // matched L1 / GIoU / cls correction
                float na0=bx[0]/S_IMG,na1=bx[1]/S_IMG,na2=bx[2]/S_IMG,na3=bx[3]/S_IMG;
                float ng0=gb[0]/S_IMG,ng1=gb[1]/S_IMG,ng2=gb[2]/S_IMG,ng3=gb[3]/S_IMG;
                double l1=(double)(fabsf(na0-ng0)+fabsf(na1-ng1)+fabsf(na2-ng2)+fabsf(na3-ng3));
                double gl=(double)(1.f-giou_pair(na0,na1,na2,na3,ng0,ng1,ng2,ng3));
                int mcls=gcls[b*MM+j];
                float x=logits[(size_t)id*CC+mcls];
                float p=1.f/(1.f+expf(-x));
                float sp=fmaxf(x,0.f)+log1pf(expf(-fabsf(x)));
                float posv=0.25f*(1.f-p)*(1.f-p)*(sp-x);
                float negv=0.75f*p*p*sp;
                atomicAdd(&g_accb[bank][0],(double)(posv-negv));
                atomicAdd(&g_accb[bank][1],l1);
                atomicAdd(&g_accb[bank][2],gl);
                atomicAdd(&g_accb[bank][3],dice);
                atomicAdd(&g_accb[bank][4],1.0);
            }
        }
    } else {
        // ---- negative-class focal bulk ----
        int base=(blk-PROP_BLKS)*1280 + tid;
        double cl=0.0;
        #pragma unroll
        for(int k=0;k<5;k++){
            int e=base+k*256;
            float x=logits[e];
            float p=1.f/(1.f+__expf(-x));
            float sp=fmaxf(x,0.f)+log1pf(__expf(-fabsf(x)));
            cl += (double)(0.75f*p*p*sp);
        }
        #pragma unroll
        for(int off=16;off;off>>=1) cl+=__shfl_down_sync(0xffffffffu,cl,off);
        __shared__ double sred[8];
        if(lane==0) sred[warp]=cl;
        __syncthreads();
        if(tid==0){
            double a=0;
            #pragma unroll
            for(int w=0;w<8;w++) a+=sred[w];
            atomicAdd(&g_accb[bank][0],a);
        }
    }

    // ---- ticket: last finished block finalizes ----
    __shared__ int amlast;
    __threadfence();
    if(threadIdx.x==0){
        int t=atomicAdd(&g_done,1);
        amlast=(t==(int)gridDim.x-1);
    }
    __syncthreads();
    if(amlast && threadIdx.x==0){
        __threadfence();
        double a0=0,a1=0,a2=0,a3=0,a4=0;
        #pragma unroll
        for(int k=0;k<32;k++){
            a0+=g_accb[k][0]; a1+=g_accb[k][1]; a2+=g_accb[k][2];
            a3+=g_accb[k][3]; a4+=g_accb[k][4];
        }
        out[0]=(float)(2.0*a0/a4);
        out[1]=(float)(5.0*a1/a4);
        out[2]=(float)(2.0*a2/a4);
        out[3]=(float)(5.0*a3/a4);
        g_done=0;
    }
}

extern "C" void kernel_launch(void* const* d_in, const int* in_sizes, int n_in,
                              void* d_out, int out_size){
    const float* logits=(const float*)d_in[0];
    const float* boxes =(const float*)d_in[1];
    const float* feat  =(const float*)d_in[2];
    const float* wmask =(const float*)d_in[3];
    const int*   gcls  =(const int*)  d_in[4];
    const float* gbox  =(const float*)d_in[5];
    const float* gmask =(const float*)d_in[6];
    float* out=(float*)d_out;

    k_stage1<<<K1_GRID,256>>>(logits,boxes,feat,wmask,gcls,gbox);
    k_stage2<<<K2_GRID,256>>>(logits,boxes,gcls,gbox,gmask,out);
}

// round 5
// speedup vs baseline: 3.0187x; 1.0053x over previous
#include <cuda_runtime.h>
#include <math.h>

#define BB 4
#define NN 300
#define CC 80
#define MM 24
#define CF 128
#define HF 64
#define HM 224
#define TT 28

#define S_IMG 896.0f
#define CENTER_R 44.8f
#define EPSF 1e-8f

#define PROJ_BLKS  64
#define COL_BLKS   (BB*MM)          // 96
#define GRID       (PROJ_BLKS+COL_BLKS)   // 160
#define NEG_TOT    (BB*NN*CC)       // 96000
#define NEG_PER    (NEG_TOT/GRID)   // 600

// ---------------- scratch ----------------
__device__ float  g_proj[BB*MM*HF*HF];
__device__ float  g_costT[BB*NN*MM];
__device__ unsigned char g_matchT[BB*NN*MM];
__device__ int    g_valid[BB*NN];
__device__ float  g_gcrop[BB*MM*TT*TT];   // cached gt-mask crops (per gt, not per proposal!)
__device__ float  g_gsum[BB*MM];
__device__ double g_accb[32][5] = {};     // banked: cls, l1, giou, mask, ninst
__device__ int    g_bar = 0;
__device__ int    g_done = 0;

// ---------------- helpers ----------------
__device__ __forceinline__ float sigm(float x){ return 1.f/(1.f+expf(-x)); }

__device__ __forceinline__ float iou_exact(float ax1,float ay1,float ax2,float ay2,
                                           float bx1,float by1,float bx2,float by2){
    float ltx=fmaxf(ax1,bx1), lty=fmaxf(ay1,by1);
    float rbx=fminf(ax2,bx2), rby=fminf(ay2,by2);
    float w=fmaxf(__fsub_rn(rbx,ltx),0.f), h=fmaxf(__fsub_rn(rby,lty),0.f);
    float inter=__fmul_rn(w,h);
    float aA=__fmul_rn(fmaxf(__fsub_rn(ax2,ax1),0.f), fmaxf(__fsub_rn(ay2,ay1),0.f));
    float aB=__fmul_rn(fmaxf(__fsub_rn(bx2,bx1),0.f), fmaxf(__fsub_rn(by2,by1),0.f));
    float uni=__fsub_rn(__fadd_rn(aA,aB), inter);
    return __fdiv_rn(inter, __fadd_rn(uni, EPSF));
}

__device__ __forceinline__ float giou_pair(float a0,float a1,float a2,float a3,
                                           float g0,float g1,float g2,float g3){
    float ltx=fmaxf(a0,g0), lty=fmaxf(a1,g1);
    float rbx=fminf(a2,g2), rby=fminf(a3,g3);
    float w=fmaxf(rbx-ltx,0.f), h=fmaxf(rby-lty,0.f);
    float inter=w*h;
    float aA=fmaxf(a2-a0,0.f)*fmaxf(a3-a1,0.f);
    float aB=fmaxf(g2-g0,0.f)*fmaxf(g3-g1,0.f);
    float uni=aA+aB-inter;
    float iou=inter/(uni+EPSF);
    float ex=fminf(a0,g0), ey=fminf(a1,g1);
    float fx=fmaxf(a2,g2), fy=fmaxf(a3,g3);
    float enc=fmaxf(fx-ex,0.f)*fmaxf(fy-ey,0.f);
    return iou-(enc-uni)/(enc+EPSF);
}

__device__ __forceinline__ float bilerp(const float* img,int W,int H,float X,float Y){
    float x0f=fminf(fmaxf(floorf(X),0.f),(float)(W-1));
    float y0f=fminf(fmaxf(floorf(Y),0.f),(float)(H-1));
    float wx=fminf(fmaxf(X-x0f,0.f),1.f);
    float wy=fminf(fmaxf(Y-y0f,0.f),1.f);
    int x0=(int)x0f, y0=(int)y0f;
    int x1=min(x0+1,W-1), y1=min(y0+1,H-1);
    float g00=img[y0*W+x0], g01=img[y0*W+x1];
    float g10=img[y1*W+x0], g11=img[y1*W+x1];
    return g00*(1.f-wx)*(1.f-wy)+g01*wx*(1.f-wy)+g10*(1.f-wx)*wy+g11*wx*wy;
}

// ================= single persistent kernel =================
__global__ void __launch_bounds__(256,2)
k_all(const float* __restrict__ logits, const float* __restrict__ boxes,
      const float* __restrict__ feat,   const float* __restrict__ wmask,
      const int*   __restrict__ gcls,   const float* __restrict__ gbox,
      const float* __restrict__ gmask,  float* __restrict__ out){
    int blk=blockIdx.x, tid=threadIdx.x;
    int lane=tid&31, warp=tid>>5;
    int bank=blk&31;

    __shared__ float s_f[MM*CF];           // proj weights OR (column) reuse space
    __shared__ float col[NN];
    __shared__ unsigned char sval[NN];
    __shared__ float sg[MM][4];
    __shared__ float wtop[8][10];
    __shared__ int   s_dk;
    __shared__ double sred[8];

    // =================== STAGE 1 ===================
    if(blk < PROJ_BLKS){
        // ---- projected class maps ----
        int b=blk/16;
        for(int idx=tid; idx<MM*CF; idx+=256){
            int j=idx/CF, f=idx%CF;
            s_f[idx]=wmask[gcls[b*MM+j]*CF+f];
        }
        __syncthreads();
        int pix=(blk%16)*256+tid;
        float acc[MM];
        #pragma unroll
        for(int j=0;j<MM;j++) acc[j]=0.f;
        const float* fb = feat + ((size_t)b*CF)*(HF*HF) + pix;
        for(int f=0;f<CF;f++){
            float v=fb[(size_t)f*(HF*HF)];
            #pragma unroll
            for(int j=0;j<MM;j++) acc[j] += v*s_f[j*CF+f];
        }
        #pragma unroll
        for(int j=0;j<MM;j++) g_proj[((b*MM+j)*(HF*HF))+pix]=acc[j];
    } else {
        // ---- one cost column + dynk + rank + gcrop cache ----
        int idx=blk-PROJ_BLKS;
        int b=idx/MM, j=idx%MM;
        if(tid<MM){
            sg[tid][0]=gbox[(b*MM+tid)*4+0]; sg[tid][1]=gbox[(b*MM+tid)*4+1];
            sg[tid][2]=gbox[(b*MM+tid)*4+2]; sg[tid][3]=gbox[(b*MM+tid)*4+3];
        }
        __syncthreads();
        float gx1=sg[j][0],gy1=sg[j][1],gx2=sg[j][2],gy2=sg[j][3];
        float gcx=(gx1+gx2)*0.5f, gcy=(gy1+gy2)*0.5f;
        int cls_j=gcls[b*MM+j];
        float ng0=gx1/S_IMG,ng1=gy1/S_IMG,ng2=gx2/S_IMG,ng3=gy2/S_IMG;
        float loc[10];
        #pragma unroll
        for(int k=0;k<10;k++) loc[k]=-1e30f;
        for(int i=tid;i<NN;i+=256){
            const float* bx=&boxes[(size_t)(b*NN+i)*4];
            float ax1=bx[0],ay1=bx[1],ax2=bx[2],ay2=bx[3];
            float cx=(ax1+ax2)*0.5f, cy=(ay1+ay2)*0.5f;
            int any=0;
            #pragma unroll 4
            for(int q=0;q<MM;q++){
                float qx1=sg[q][0],qy1=sg[q][1],qx2=sg[q][2],qy2=sg[q][3];
                bool igt=(cx>=qx1)&&(cx<=qx2)&&(cy>=qy1)&&(cy<=qy2);
                bool ict=(fabsf(cx-(qx1+qx2)*0.5f)<=CENTER_R)&&(fabsf(cy-(qy1+qy2)*0.5f)<=CENTER_R);
                any |= (igt||ict);
            }
            sval[i]=(unsigned char)any;
            g_valid[b*NN+i]=any;
            float x=logits[(size_t)(b*NN+i)*CC + cls_j];
            float p=sigm(x);
            float neg=-logf(1.f-p+EPSF)*0.75f*p*p;
            float pos=-logf(p+EPSF)*0.25f*(1.f-p)*(1.f-p);
            float cls_cost=2.f*(pos-neg);
            float na0=ax1/S_IMG,na1=ay1/S_IMG,na2=ax2/S_IMG,na3=ay2/S_IMG;
            float l1c=5.f*(fabsf(na0-ng0)+fabsf(na1-ng1)+fabsf(na2-ng2)+fabsf(na3-ng3));
            float ngiou=giou_pair(na0,na1,na2,na3,ng0,ng1,ng2,ng3);
            bool ingt=(cx>=gx1)&&(cx<=gx2)&&(cy>=gy1)&&(cy<=gy2);
            bool inct=(fabsf(cx-gcx)<=CENTER_R)&&(fabsf(cy-gcy)<=CENTER_R);
            float cost=cls_cost+l1c+2.f*(1.f-ngiou);
            cost += (ingt&&inct)?0.f:1e5f;
            cost += any?0.f:1e9f;
            col[i]=cost;
            g_costT[(size_t)(b*NN+i)*MM+j]=cost;
            float iou=iou_exact(ax1,ay1,ax2,ay2,gx1,gy1,gx2,gy2);
            float v=any? iou : 0.f;
            if(v>loc[9]){
                int k=9;
                #pragma unroll
                for(int q=9;q>0;q--){
                    if(loc[q-1]<v){ loc[q]=loc[q-1]; k=q-1; } else break;
                }
                loc[k]=v;
            }
        }
        // warp top-10 merge
        {
            int p=0; float out10[10];
            #pragma unroll
            for(int r=0;r<10;r++){
                float h=(p<10)?loc[p]:-1e30f;
                float m=h;
                #pragma unroll
                for(int off=16;off;off>>=1)
                    m=fmaxf(m,__shfl_xor_sync(0xffffffffu,m,off));
                out10[r]=m;
                unsigned ball=__ballot_sync(0xffffffffu, h==m);
                if(lane==(__ffs(ball)-1)) p++;
            }
            if(lane==0){
                #pragma unroll
                for(int r=0;r<10;r++) wtop[warp][r]=out10[r];
            }
        }
        __syncthreads();
        if(warp==0){
            int p=0; float s=0.f;
            #pragma unroll
            for(int r=0;r<10;r++){
                float h=(lane<8 && p<10)? wtop[lane][p] : -1e30f;
                float m=h;
                #pragma unroll
                for(int off=16;off;off>>=1)
                    m=fmaxf(m,__shfl_xor_sync(0xffffffffu,m,off));
                s+=m;
                unsigned ball=__ballot_sync(0xffffffffu, h==m && lane<8);
                if(lane==(__ffs(ball)-1)) p++;
            }
            if(lane==0){
                int dk=(int)s;
                if(dk<1)dk=1; if(dk>NN)dk=NN;
                s_dk=dk;
            }
        }
        __syncthreads();
        int dk=s_dk;
        for(int i=tid;i<NN;i+=256){
            float myc=col[i];
            int r=0;
            #pragma unroll 4
            for(int k=0;k<NN;k++){
                float ck=col[k];
                r += (ck<myc) || (ck==myc && k<i);
            }
            g_matchT[(size_t)(b*NN+i)*MM+j]=(unsigned char)((r<dk) && sval[i]);
        }
        // ---- gcrop cache: crop_resize(gt_mask[j], gbox[j]) — per GT, shared by all proposals ----
        {
            const float* gm=&gmask[(size_t)(b*MM+j)*(HM*HM)];
            float qx1=gx1*0.25f, qy1=gy1*0.25f, qx2=gx2*0.25f, qy2=gy2*0.25f;
            float gs=0.f;
            for(int pix=tid; pix<TT*TT; pix+=256){
                int ty=pix/TT, tx=pix%TT;
                float ux=((float)tx+0.5f)/28.f, uy=((float)ty+0.5f)/28.f;
                float Xg=qx1+(qx2-qx1)*ux-0.5f, Yg=qy1+(qy2-qy1)*uy-0.5f;
                float gv=bilerp(gm,HM,HM,Xg,Yg);
                g_gcrop[(size_t)(b*MM+j)*(TT*TT)+pix]=gv;
                gs+=gv;
            }
            #pragma unroll
            for(int off=16;off;off>>=1) gs+=__shfl_down_sync(0xffffffffu,gs,off);
            if(lane==0) ((double*)sred)[warp]=(double)gs;   // reuse sred as float-safe slot
            __syncthreads();
            if(tid==0){
                double t=0;
                #pragma unroll
                for(int w=0;w<8;w++) t+=((double*)sred)[w];
                g_gsum[b*MM+j]=(float)t;
            }
        }
    }

    // ---- negative-class focal bulk (all blocks, 600 elements each) ----
    {
        double cl=0.0;
        for(int e=blk*NEG_PER+tid; e<(blk+1)*NEG_PER; e+=256){
            float x=logits[e];
            float p=1.f/(1.f+__expf(-x));
            float sp=fmaxf(x,0.f)+log1pf(__expf(-fabsf(x)));
            cl += (double)(0.75f*p*p*sp);
        }
        #pragma unroll
        for(int off=16;off;off>>=1) cl+=__shfl_down_sync(0xffffffffu,cl,off);
        __syncthreads();
        if(lane==0) sred[warp]=cl;
        __syncthreads();
        if(tid==0){
            double a=0;
            #pragma unroll
            for(int w=0;w<8;w++) a+=sred[w];
            atomicAdd(&g_accb[bank][0],a);
        }
    }

    // =================== device-wide barrier ===================
    __syncthreads();
    __threadfence();
    if(tid==0){
        atomicAdd(&g_bar,1);
        while(*(volatile int*)&g_bar < GRID) { }
    }
    __syncthreads();
    __threadfence();

    // =================== STAGE 2: warp per proposal ===================
    {
        int w = blk*8 + warp;          // 1280 warps for 1200 proposals
        if(w < BB*NN && g_valid[w]){
            int b=w/NN;
            // inline assignment
            float c=(lane<MM)? g_costT[(size_t)w*MM+lane] : 3.4e38f;
            unsigned char mb=(lane<MM)? g_matchT[(size_t)w*MM+lane] : 0;
            unsigned bits=__ballot_sync(0xffffffffu, lane<MM && mb);
            float bv=c; int bi=lane;
            #pragma unroll
            for(int off=16;off;off>>=1){
                float ov=__shfl_down_sync(0xffffffffu,bv,off);
                int   oi=__shfl_down_sync(0xffffffffu,bi,off);
                if(ov<bv || (ov==bv && oi<bi)){bv=ov;bi=oi;}
            }
            int best=__shfl_sync(0xffffffffu,bi,0);
            int cnt=__popc(bits);
            int j=(cnt==1)? (__ffs(bits)-1) : best;

            const float* pj=&g_proj[(size_t)(b*MM+j)*(HF*HF)];
            const float* gc=&g_gcrop[(size_t)(b*MM+j)*(TT*TT)];
            const float* bx=&boxes[(size_t)w*4];
            const float* gb=&gbox[(size_t)(b*MM+j)*4];
            const float FS=(float)(64.0/896.0);
            float px1=bx[0]*FS, py1=bx[1]*FS, px2=bx[2]*FS, py2=bx[3]*FS;
            float inter=0.f, sm=0.f;
            for(int pix=lane; pix<TT*TT; pix+=32){
                int ty=pix/TT, tx=pix%TT;
                float ux=((float)tx+0.5f)/28.f, uy=((float)ty+0.5f)/28.f;
                float X=px1+(px2-px1)*ux-0.5f, Y=py1+(py2-py1)*uy-0.5f;
                float z=bilerp(pj,HF,HF,X,Y);
                float mv=1.f/(1.f+__expf(-z));
                float gv=gc[pix];
                inter+=mv*gv; sm+=mv;
            }
            #pragma unroll
            for(int off=16;off;off>>=1){
                inter+=__shfl_down_sync(0xffffffffu,inter,off);
                sm   +=__shfl_down_sync(0xffffffffu,sm,off);
            }
            if(lane==0){
                float sgv=g_gsum[b*MM+j];
                double dice=(double)(1.f-2.f*inter/(sm+sgv+EPSF));
                float na0=bx[0]/S_IMG,na1=bx[1]/S_IMG,na2=bx[2]/S_IMG,na3=bx[3]/S_IMG;
                float ng0=gb[0]/S_IMG,ng1=gb[1]/S_IMG,ng2=gb[2]/S_IMG,ng3=gb[3]/S_IMG;
                double l1=(double)(fabsf(na0-ng0)+fabsf(na1-ng1)+fabsf(na2-ng2)+fabsf(na3-ng3));
                double gl=(double)(1.f-giou_pair(na0,na1,na2,na3,ng0,ng1,ng2,ng3));
                int mcls=gcls[b*MM+j];
                float x=logits[(size_t)w*CC+mcls];
                float p=1.f/(1.f+expf(-x));
                float sp=fmaxf(x,0.f)+log1pf(expf(-fabsf(x)));
                float posv=0.25f*(1.f-p)*(1.f-p)*(sp-x);
                float negv=0.75f*p*p*sp;
                atomicAdd(&g_accb[bank][0],(double)(posv-negv));
                atomicAdd(&g_accb[bank][1],l1);
                atomicAdd(&g_accb[bank][2],gl);
                atomicAdd(&g_accb[bank][3],dice);
                atomicAdd(&g_accb[bank][4],1.0);
            }
        }
    }

    // =================== ticket finalize + state reset ===================
    __syncthreads();
    __threadfence();
    if(tid==0){
        int t=atomicAdd(&g_done,1);
        if(t==GRID-1){
            __threadfence();
            double a0=0,a1=0,a2=0,a3=0,a4=0;
            #pragma unroll
            for(int k=0;k<32;k++){
                a0+=g_accb[k][0]; a1+=g_accb[k][1]; a2+=g_accb[k][2];
                a3+=g_accb[k][3]; a4+=g_accb[k][4];
                g_accb[k][0]=0.0; g_accb[k][1]=0.0; g_accb[k][2]=0.0;
                g_accb[k][3]=0.0; g_accb[k][4]=0.0;
            }
            out[0]=(float)(2.0*a0/a4);
            out[1]=(float)(5.0*a1/a4);
            out[2]=(float)(2.0*a2/a4);
            out[3]=(float)(5.0*a3/a4);
            g_done=0;
            g_bar=0;
        }
    }
}

extern "C" void kernel_launch(void* const* d_in, const int* in_sizes, int n_in,
                              void* d_out, int out_size){
    const float* logits=(const float*)d_in[0];
    const float* boxes =(const float*)d_in[1];
    const float* feat  =(const float*)d_in[2];
    const float* wmask =(const float*)d_in[3];
    const int*   gcls  =(const int*)  d_in[4];
    const float* gbox  =(const float*)d_in[5];
    const float* gmask =(const float*)d_in[6];
    float* out=(float*)d_out;

    k_all<<<GRID,256>>>(logits,boxes,feat,wmask,gcls,gbox,gmask,out);
}

// round 6
// speedup vs baseline: 3.3983x; 1.1258x over previous
#include <cuda_runtime.h>
#include <math.h>

#define BB 4
#define NN 300
#define CC 80
#define MM 24
#define CF 128
#define HF 64
#define HM 224
#define TT 28

#define S_IMG 896.0f
#define CENTER_R 44.8f
#define EPSF 1e-8f

#define PROJ_BLKS  64
#define COL_BLKS   (BB*MM)                  // 96
#define NEG_BLKS   75                       // 75*1280 = 96000 = BB*NN*CC
#define K1_GRID    (PROJ_BLKS+COL_BLKS+NEG_BLKS)   // 235
#define K2_GRID    150                      // 150*8 warps >= 1200 proposals

// ---------------- scratch ----------------
__device__ float  g_proj[BB*MM*HF*HF];
__device__ float  g_costT[BB*NN*MM];
__device__ unsigned char g_matchT[BB*NN*MM];
__device__ int    g_valid[BB*NN];
__device__ float  g_gcrop[BB*MM*TT*TT];
__device__ float  g_gsum[BB*MM];
__device__ double g_accb[32][5] = {};       // banked: cls, l1, giou, mask, ninst
__device__ int    g_done = 0;

// ---------------- helpers ----------------
__device__ __forceinline__ float sigm(float x){ return 1.f/(1.f+expf(-x)); }

__device__ __forceinline__ float iou_exact(float ax1,float ay1,float ax2,float ay2,
                                           float bx1,float by1,float bx2,float by2){
    float ltx=fmaxf(ax1,bx1), lty=fmaxf(ay1,by1);
    float rbx=fminf(ax2,bx2), rby=fminf(ay2,by2);
    float w=fmaxf(__fsub_rn(rbx,ltx),0.f), h=fmaxf(__fsub_rn(rby,lty),0.f);
    float inter=__fmul_rn(w,h);
    float aA=__fmul_rn(fmaxf(__fsub_rn(ax2,ax1),0.f), fmaxf(__fsub_rn(ay2,ay1),0.f));
    float aB=__fmul_rn(fmaxf(__fsub_rn(bx2,bx1),0.f), fmaxf(__fsub_rn(by2,by1),0.f));
    float uni=__fsub_rn(__fadd_rn(aA,aB), inter);
    return __fdiv_rn(inter, __fadd_rn(uni, EPSF));
}

__device__ __forceinline__ float giou_pair(float a0,float a1,float a2,float a3,
                                           float g0,float g1,float g2,float g3){
    float ltx=fmaxf(a0,g0), lty=fmaxf(a1,g1);
    float rbx=fminf(a2,g2), rby=fminf(a3,g3);
    float w=fmaxf(rbx-ltx,0.f), h=fmaxf(rby-lty,0.f);
    float inter=w*h;
    float aA=fmaxf(a2-a0,0.f)*fmaxf(a3-a1,0.f);
    float aB=fmaxf(g2-g0,0.f)*fmaxf(g3-g1,0.f);
    float uni=aA+aB-inter;
    float iou=inter/(uni+EPSF);
    float ex=fminf(a0,g0), ey=fminf(a1,g1);
    float fx=fmaxf(a2,g2), fy=fmaxf(a3,g3);
    float enc=fmaxf(fx-ex,0.f)*fmaxf(fy-ey,0.f);
    return iou-(enc-uni)/(enc+EPSF);
}

__device__ __forceinline__ float bilerp(const float* img,int W,int H,float X,float Y){
    float x0f=fminf(fmaxf(floorf(X),0.f),(float)(W-1));
    float y0f=fminf(fmaxf(floorf(Y),0.f),(float)(H-1));
    float wx=fminf(fmaxf(X-x0f,0.f),1.f);
    float wy=fminf(fmaxf(Y-y0f,0.f),1.f);
    int x0=(int)x0f, y0=(int)y0f;
    int x1=min(x0+1,W-1), y1=min(y0+1,H-1);
    float g00=img[y0*W+x0], g01=img[y0*W+x1];
    float g10=img[y1*W+x0], g11=img[y1*W+x1];
    return g00*(1.f-wx)*(1.f-wy)+g01*wx*(1.f-wy)+g10*(1.f-wx)*wy+g11*wx*wy;
}

// ================= K1: proj (smem-staged) || columns || neg focal =================
__global__ void __launch_bounds__(256)
k_stage1(const float* __restrict__ logits, const float* __restrict__ boxes,
         const float* __restrict__ feat,   const float* __restrict__ wmask,
         const int*   __restrict__ gcls,   const float* __restrict__ gbox,
         const float* __restrict__ gmask){
    int blk=blockIdx.x, tid=threadIdx.x;
    int lane=tid&31, warp=tid>>5;
    int bank=blk&31;

    if(blk < PROJ_BLKS){
        // ---- projected class maps, smem-staged feat for MLP ----
        __shared__ float wm[MM*CF];      // 12 KB
        __shared__ float sf[16*256];     // 16 KB: 16 f-rows x 256 px
        int b=blk/16, chunk=blk%16;
        int px0=chunk*256;
        for(int idx=tid; idx<MM*CF; idx+=256){
            int j=idx/CF, f=idx%CF;
            wm[idx]=wmask[gcls[b*MM+j]*CF+f];
        }
        float acc[MM];
        #pragma unroll
        for(int j=0;j<MM;j++) acc[j]=0.f;
        const float* fb = feat + ((size_t)b*CF)*(HF*HF) + px0;
        for(int fc=0; fc<8; fc++){
            __syncthreads();
            // cooperative coalesced stage: 16 rows, each thread issues 16 independent loads
            #pragma unroll
            for(int k=0;k<16;k++)
                sf[k*256+tid]=fb[(size_t)(fc*16+k)*(HF*HF)+tid];
            __syncthreads();
            #pragma unroll
            for(int k=0;k<16;k++){
                float v=sf[k*256+tid];
                const float* w0=&wm[fc*16+k];
                #pragma unroll
                for(int j=0;j<MM;j++) acc[j] += v*w0[j*CF];
            }
        }
        #pragma unroll
        for(int j=0;j<MM;j++) g_proj[((b*MM+j)*(HF*HF))+px0+tid]=acc[j];
        return;
    }

    if(blk < PROJ_BLKS+COL_BLKS){
        // ---- one cost column + dynk + rank + gcrop cache ----
        int idx=blk-PROJ_BLKS;
        int b=idx/MM, j=idx%MM;
        __shared__ float col[NN];
        __shared__ unsigned char sval[NN];
        __shared__ float sg[MM][4];
        __shared__ float wtop[8][10];
        __shared__ int   s_dk;
        __shared__ double sred[8];
        if(tid<MM){
            sg[tid][0]=gbox[(b*MM+tid)*4+0]; sg[tid][1]=gbox[(b*MM+tid)*4+1];
            sg[tid][2]=gbox[(b*MM+tid)*4+2]; sg[tid][3]=gbox[(b*MM+tid)*4+3];
        }
        __syncthreads();
        float gx1=sg[j][0],gy1=sg[j][1],gx2=sg[j][2],gy2=sg[j][3];
        float gcx=(gx1+gx2)*0.5f, gcy=(gy1+gy2)*0.5f;
        int cls_j=gcls[b*MM+j];
        float ng0=gx1/S_IMG,ng1=gy1/S_IMG,ng2=gx2/S_IMG,ng3=gy2/S_IMG;
        float loc[10];
        #pragma unroll
        for(int k=0;k<10;k++) loc[k]=-1e30f;
        for(int i=tid;i<NN;i+=256){
            const float* bx=&boxes[(size_t)(b*NN+i)*4];
            float ax1=bx[0],ay1=bx[1],ax2=bx[2],ay2=bx[3];
            float cx=(ax1+ax2)*0.5f, cy=(ay1+ay2)*0.5f;
            int any=0;
            #pragma unroll 4
            for(int q=0;q<MM;q++){
                float qx1=sg[q][0],qy1=sg[q][1],qx2=sg[q][2],qy2=sg[q][3];
                bool igt=(cx>=qx1)&&(cx<=qx2)&&(cy>=qy1)&&(cy<=qy2);
                bool ict=(fabsf(cx-(qx1+qx2)*0.5f)<=CENTER_R)&&(fabsf(cy-(qy1+qy2)*0.5f)<=CENTER_R);
                any |= (igt||ict);
            }
            sval[i]=(unsigned char)any;
            g_valid[b*NN+i]=any;
            float x=logits[(size_t)(b*NN+i)*CC + cls_j];
            float p=sigm(x);
            float neg=-logf(1.f-p+EPSF)*0.75f*p*p;
            float pos=-logf(p+EPSF)*0.25f*(1.f-p)*(1.f-p);
            float cls_cost=2.f*(pos-neg);
            float na0=ax1/S_IMG,na1=ay1/S_IMG,na2=ax2/S_IMG,na3=ay2/S_IMG;
            float l1c=5.f*(fabsf(na0-ng0)+fabsf(na1-ng1)+fabsf(na2-ng2)+fabsf(na3-ng3));
            float ngiou=giou_pair(na0,na1,na2,na3,ng0,ng1,ng2,ng3);
            bool ingt=(cx>=gx1)&&(cx<=gx2)&&(cy>=gy1)&&(cy<=gy2);
            bool inct=(fabsf(cx-gcx)<=CENTER_R)&&(fabsf(cy-gcy)<=CENTER_R);
            float cost=cls_cost+l1c+2.f*(1.f-ngiou);
            cost += (ingt&&inct)?0.f:1e5f;
            cost += any?0.f:1e9f;
            col[i]=cost;
            g_costT[(size_t)(b*NN+i)*MM+j]=cost;
            float iou=iou_exact(ax1,ay1,ax2,ay2,gx1,gy1,gx2,gy2);
            float v=any? iou : 0.f;
            if(v>loc[9]){
                int k=9;
                #pragma unroll
                for(int q=9;q>0;q--){
                    if(loc[q-1]<v){ loc[q]=loc[q-1]; k=q-1; } else break;
                }
                loc[k]=v;
            }
        }
        // warp top-10 merge
        {
            int p=0; float out10[10];
            #pragma unroll
            for(int r=0;r<10;r++){
                float h=(p<10)?loc[p]:-1e30f;
                float m=h;
                #pragma unroll
                for(int off=16;off;off>>=1)
                    m=fmaxf(m,__shfl_xor_sync(0xffffffffu,m,off));
                out10[r]=m;
                unsigned ball=__ballot_sync(0xffffffffu, h==m);
                if(lane==(__ffs(ball)-1)) p++;
            }
            if(lane==0){
                #pragma unroll
                for(int r=0;r<10;r++) wtop[warp][r]=out10[r];
            }
        }
        __syncthreads();
        if(warp==0){
            int p=0; float s=0.f;
            #pragma unroll
            for(int r=0;r<10;r++){
                float h=(lane<8 && p<10)? wtop[lane][p] : -1e30f;
                float m=h;
                #pragma unroll
                for(int off=16;off;off>>=1)
                    m=fmaxf(m,__shfl_xor_sync(0xffffffffu,m,off));
                s+=m;
                unsigned ball=__ballot_sync(0xffffffffu, h==m && lane<8);
                if(lane==(__ffs(ball)-1)) p++;
            }
            if(lane==0){
                int dk=(int)s;
                if(dk<1)dk=1; if(dk>NN)dk=NN;
                s_dk=dk;
            }
        }
        __syncthreads();
        int dk=s_dk;
        for(int i=tid;i<NN;i+=256){
            float myc=col[i];
            int r=0;
            #pragma unroll 4
            for(int k=0;k<NN;k++){
                float ck=col[k];
                r += (ck<myc) || (ck==myc && k<i);
            }
            g_matchT[(size_t)(b*NN+i)*MM+j]=(unsigned char)((r<dk) && sval[i]);
        }
        // ---- gcrop cache (per GT) ----
        {
            const float* gm=&gmask[(size_t)(b*MM+j)*(HM*HM)];
            float qx1=gx1*0.25f, qy1=gy1*0.25f, qx2=gx2*0.25f, qy2=gy2*0.25f;
            float gs=0.f;
            for(int pix=tid; pix<TT*TT; pix+=256){
                int ty=pix/TT, tx=pix%TT;
                float ux=((float)tx+0.5f)/28.f, uy=((float)ty+0.5f)/28.f;
                float Xg=qx1+(qx2-qx1)*ux-0.5f, Yg=qy1+(qy2-qy1)*uy-0.5f;
                float gv=bilerp(gm,HM,HM,Xg,Yg);
                g_gcrop[(size_t)(b*MM+j)*(TT*TT)+pix]=gv;
                gs+=gv;
            }
            #pragma unroll
            for(int off=16;off;off>>=1) gs+=__shfl_down_sync(0xffffffffu,gs,off);
            if(lane==0) sred[warp]=(double)gs;
            __syncthreads();
            if(tid==0){
                double t=0;
                #pragma unroll
                for(int w=0;w<8;w++) t+=sred[w];
                g_gsum[b*MM+j]=(float)t;
            }
        }
        return;
    }

    // ---- negative-class focal bulk ----
    {
        __shared__ double sred2[8];
        int base=(blk-PROJ_BLKS-COL_BLKS)*1280 + tid;
        double cl=0.0;
        #pragma unroll
        for(int k=0;k<5;k++){
            int e=base+k*256;
            float x=logits[e];
            float p=1.f/(1.f+__expf(-x));
            float sp=fmaxf(x,0.f)+log1pf(__expf(-fabsf(x)));
            cl += (double)(0.75f*p*p*sp);
        }
        #pragma unroll
        for(int off=16;off;off>>=1) cl+=__shfl_down_sync(0xffffffffu,cl,off);
        if(lane==0) sred2[warp]=cl;
        __syncthreads();
        if(tid==0){
            double a=0;
            #pragma unroll
            for(int w=0;w<8;w++) a+=sred2[w];
            atomicAdd(&g_accb[bank][0],a);
        }
    }
}

// ================= K2: warp per proposal + ticket finalize =================
__global__ void __launch_bounds__(256)
k_stage2(const float* __restrict__ logits, const float* __restrict__ boxes,
         const int* __restrict__ gcls, const float* __restrict__ gbox,
         float* __restrict__ out){
    int blk=blockIdx.x, tid=threadIdx.x;
    int lane=tid&31, warp=tid>>5;
    int bank=blk&31;

    int w = blk*8 + warp;
    if(w < BB*NN && g_valid[w]){
        int b=w/NN;
        // inline assignment
        float c=(lane<MM)? g_costT[(size_t)w*MM+lane] : 3.4e38f;
        unsigned char mb=(lane<MM)? g_matchT[(size_t)w*MM+lane] : 0;
        unsigned bits=__ballot_sync(0xffffffffu, lane<MM && mb);
        float bv=c; int bi=lane;
        #pragma unroll
        for(int off=16;off;off>>=1){
            float ov=__shfl_down_sync(0xffffffffu,bv,off);
            int   oi=__shfl_down_sync(0xffffffffu,bi,off);
            if(ov<bv || (ov==bv && oi<bi)){bv=ov;bi=oi;}
        }
        int best=__shfl_sync(0xffffffffu,bi,0);
        int cnt=__popc(bits);
        int j=(cnt==1)? (__ffs(bits)-1) : best;

        const float* pj=&g_proj[(size_t)(b*MM+j)*(HF*HF)];
        const float* gc=&g_gcrop[(size_t)(b*MM+j)*(TT*TT)];
        const float* bx=&boxes[(size_t)w*4];
        const float* gb=&gbox[(size_t)(b*MM+j)*4];
        const float FS=(float)(64.0/896.0);
        float px1=bx[0]*FS, py1=bx[1]*FS, px2=bx[2]*FS, py2=bx[3]*FS;
        float inter=0.f, sm=0.f;
        for(int pix=lane; pix<TT*TT; pix+=32){
            int ty=pix/TT, tx=pix%TT;
            float ux=((float)tx+0.5f)/28.f, uy=((float)ty+0.5f)/28.f;
            float X=px1+(px2-px1)*ux-0.5f, Y=py1+(py2-py1)*uy-0.5f;
            float z=bilerp(pj,HF,HF,X,Y);
            float mv=1.f/(1.f+__expf(-z));
            float gv=gc[pix];
            inter+=mv*gv; sm+=mv;
        }
        #pragma unroll
        for(int off=16;off;off>>=1){
            inter+=__shfl_down_sync(0xffffffffu,inter,off);
            sm   +=__shfl_down_sync(0xffffffffu,sm,off);
        }
        if(lane==0){
            float sgv=g_gsum[b*MM+j];
            double dice=(double)(1.f-2.f*inter/(sm+sgv+EPSF));
            float na0=bx[0]/S_IMG,na1=bx[1]/S_IMG,na2=bx[2]/S_IMG,na3=bx[3]/S_IMG;
            float ng0=gb[0]/S_IMG,ng1=gb[1]/S_IMG,ng2=gb[2]/S_IMG,ng3=gb[3]/S_IMG;
            double l1=(double)(fabsf(na0-ng0)+fabsf(na1-ng1)+fabsf(na2-ng2)+fabsf(na3-ng3));
            double gl=(double)(1.f-giou_pair(na0,na1,na2,na3,ng0,ng1,ng2,ng3));
            int mcls=gcls[b*MM+j];
            float x=logits[(size_t)w*CC+mcls];
            float p=1.f/(1.f+expf(-x));
            float sp=fmaxf(x,0.f)+log1pf(expf(-fabsf(x)));
            float posv=0.25f*(1.f-p)*(1.f-p)*(sp-x);
            float negv=0.75f*p*p*sp;
            atomicAdd(&g_accb[bank][0],(double)(posv-negv));
            atomicAdd(&g_accb[bank][1],l1);
            atomicAdd(&g_accb[bank][2],gl);
            atomicAdd(&g_accb[bank][3],dice);
            atomicAdd(&g_accb[bank][4],1.0);
        }
    }

    // ---- ticket: last finished block finalizes + resets for next replay ----
    __syncthreads();
    __threadfence();
    if(tid==0){
        int t=atomicAdd(&g_done,1);
        if(t==(int)gridDim.x-1){
            __threadfence();
            double a0=0,a1=0,a2=0,a3=0,a4=0;
            #pragma unroll
            for(int k=0;k<32;k++){
                a0+=g_accb[k][0]; a1+=g_accb[k][1]; a2+=g_accb[k][2];
                a3+=g_accb[k][3]; a4+=g_accb[k][4];
                g_accb[k][0]=0.0; g_accb[k][1]=0.0; g_accb[k][2]=0.0;
                g_accb[k][3]=0.0; g_accb[k][4]=0.0;
            }
            out[0]=(float)(2.0*a0/a4);
            out[1]=(float)(5.0*a1/a4);
            out[2]=(float)(2.0*a2/a4);
            out[3]=(float)(5.0*a3/a4);
            g_done=0;
        }
    }
}

extern "C" void kernel_launch(void* const* d_in, const int* in_sizes, int n_in,
                              void* d_out, int out_size){
    const float* logits=(const float*)d_in[0];
    const float* boxes =(const float*)d_in[1];
    const float* feat  =(const float*)d_in[2];
    const float* wmask =(const float*)d_in[3];
    const int*   gcls  =(const int*)  d_in[4];
    const float* gbox  =(const float*)d_in[5];
    const float* gmask =(const float*)d_in[6];
    float* out=(float*)d_out;

    k_stage1<<<K1_GRID,256>>>(logits,boxes,feat,wmask,gcls,gbox,gmask);
    k_stage2<<<K2_GRID,256>>>(logits,boxes,gcls,gbox,out);
}

// round 7
// speedup vs baseline: 3.4972x; 1.0291x over previous
#include <cuda_runtime.h>
#include <math.h>

#define BB 4
#define NN 300
#define CC 80
#define MM 24
#define CF 128
#define HF 64
#define HM 224
#define TT 28

#define S_IMG 896.0f
#define CENTER_R 44.8f
#define EPSF 1e-8f

#define PROJ_BLKS  64
#define COL_BLKS   (BB*MM)                  // 96
#define NEG_BLKS   75                       // 75*1280 = 96000 = BB*NN*CC
#define K1_GRID    (PROJ_BLKS+COL_BLKS+NEG_BLKS)   // 235
#define K2_GRID    300                      // 300 blocks * 4 proposals (2 warps each)

// ---------------- scratch ----------------
__device__ float  g_proj[BB*MM*HF*HF];
__device__ float  g_costT[BB*NN*MM];
__device__ unsigned char g_matchT[BB*NN*MM];
__device__ int    g_valid[BB*NN];
__device__ float  g_gcrop[BB*MM*TT*TT];
__device__ float  g_gsum[BB*MM];
__device__ double g_accb[32][5] = {};       // banked: cls, l1, giou, mask, ninst
__device__ int    g_done = 0;

// ---------------- helpers ----------------
__device__ __forceinline__ float sigm(float x){ return 1.f/(1.f+expf(-x)); }

__device__ __forceinline__ float iou_exact(float ax1,float ay1,float ax2,float ay2,
                                           float bx1,float by1,float bx2,float by2){
    float ltx=fmaxf(ax1,bx1), lty=fmaxf(ay1,by1);
    float rbx=fminf(ax2,bx2), rby=fminf(ay2,by2);
    float w=fmaxf(__fsub_rn(rbx,ltx),0.f), h=fmaxf(__fsub_rn(rby,lty),0.f);
    float inter=__fmul_rn(w,h);
    float aA=__fmul_rn(fmaxf(__fsub_rn(ax2,ax1),0.f), fmaxf(__fsub_rn(ay2,ay1),0.f));
    float aB=__fmul_rn(fmaxf(__fsub_rn(bx2,bx1),0.f), fmaxf(__fsub_rn(by2,by1),0.f));
    float uni=__fsub_rn(__fadd_rn(aA,aB), inter);
    return __fdiv_rn(inter, __fadd_rn(uni, EPSF));
}

__device__ __forceinline__ float giou_pair(float a0,float a1,float a2,float a3,
                                           float g0,float g1,float g2,float g3){
    float ltx=fmaxf(a0,g0), lty=fmaxf(a1,g1);
    float rbx=fminf(a2,g2), rby=fminf(a3,g3);
    float w=fmaxf(rbx-ltx,0.f), h=fmaxf(rby-lty,0.f);
    float inter=w*h;
    float aA=fmaxf(a2-a0,0.f)*fmaxf(a3-a1,0.f);
    float aB=fmaxf(g2-g0,0.f)*fmaxf(g3-g1,0.f);
    float uni=aA+aB-inter;
    float iou=inter/(uni+EPSF);
    float ex=fminf(a0,g0), ey=fminf(a1,g1);
    float fx=fmaxf(a2,g2), fy=fmaxf(a3,g3);
    float enc=fmaxf(fx-ex,0.f)*fmaxf(fy-ey,0.f);
    return iou-(enc-uni)/(enc+EPSF);
}

__device__ __forceinline__ float bilerp(const float* __restrict__ img,int W,int H,float X,float Y){
    float x0f=fminf(fmaxf(floorf(X),0.f),(float)(W-1));
    float y0f=fminf(fmaxf(floorf(Y),0.f),(float)(H-1));
    float wx=fminf(fmaxf(X-x0f,0.f),1.f);
    float wy=fminf(fmaxf(Y-y0f,0.f),1.f);
    int x0=(int)x0f, y0=(int)y0f;
    int x1=min(x0+1,W-1), y1=min(y0+1,H-1);
    float g00=__ldg(&img[y0*W+x0]), g01=__ldg(&img[y0*W+x1]);
    float g10=__ldg(&img[y1*W+x0]), g11=__ldg(&img[y1*W+x1]);
    return g00*(1.f-wx)*(1.f-wy)+g01*wx*(1.f-wy)+g10*(1.f-wx)*wy+g11*wx*wy;
}

// ================= K1: proj (smem-staged) || columns || neg focal =================
__global__ void __launch_bounds__(256)
k_stage1(const float* __restrict__ logits, const float* __restrict__ boxes,
         const float* __restrict__ feat,   const float* __restrict__ wmask,
         const int*   __restrict__ gcls,   const float* __restrict__ gbox,
         const float* __restrict__ gmask){
    int blk=blockIdx.x, tid=threadIdx.x;
    int lane=tid&31, warp=tid>>5;
    int bank=blk&31;

    if(blk < PROJ_BLKS){
        __shared__ float wm[MM*CF];      // 12 KB
        __shared__ float sf[16*256];     // 16 KB
        int b=blk/16, chunk=blk%16;
        int px0=chunk*256;
        for(int idx=tid; idx<MM*CF; idx+=256){
            int j=idx/CF, f=idx%CF;
            wm[idx]=wmask[gcls[b*MM+j]*CF+f];
        }
        float acc[MM];
        #pragma unroll
        for(int j=0;j<MM;j++) acc[j]=0.f;
        const float* fb = feat + ((size_t)b*CF)*(HF*HF) + px0;
        for(int fc=0; fc<8; fc++){
            __syncthreads();
            #pragma unroll
            for(int k=0;k<16;k++)
                sf[k*256+tid]=fb[(size_t)(fc*16+k)*(HF*HF)+tid];
            __syncthreads();
            #pragma unroll
            for(int k=0;k<16;k++){
                float v=sf[k*256+tid];
                const float* w0=&wm[fc*16+k];
                #pragma unroll
                for(int j=0;j<MM;j++) acc[j] += v*w0[j*CF];
            }
        }
        #pragma unroll
        for(int j=0;j<MM;j++) g_proj[((b*MM+j)*(HF*HF))+px0+tid]=acc[j];
        return;
    }

    if(blk < PROJ_BLKS+COL_BLKS){
        // ---- one cost column + dynk + rank + gcrop cache ----
        int idx=blk-PROJ_BLKS;
        int b=idx/MM, j=idx%MM;
        __shared__ float col[NN];
        __shared__ unsigned char sval[NN];
        __shared__ float sg[MM][4];
        __shared__ float wtop[8][10];
        __shared__ int   s_dk;
        __shared__ double sred[8];
        if(tid<MM){
            sg[tid][0]=gbox[(b*MM+tid)*4+0]; sg[tid][1]=gbox[(b*MM+tid)*4+1];
            sg[tid][2]=gbox[(b*MM+tid)*4+2]; sg[tid][3]=gbox[(b*MM+tid)*4+3];
        }
        __syncthreads();
        float gx1=sg[j][0],gy1=sg[j][1],gx2=sg[j][2],gy2=sg[j][3];
        float gcx=(gx1+gx2)*0.5f, gcy=(gy1+gy2)*0.5f;
        int cls_j=gcls[b*MM+j];
        float ng0=gx1/S_IMG,ng1=gy1/S_IMG,ng2=gx2/S_IMG,ng3=gy2/S_IMG;
        float loc[10];
        #pragma unroll
        for(int k=0;k<10;k++) loc[k]=-1e30f;
        #pragma unroll 2
        for(int i=tid;i<NN;i+=256){
            const float* bx=&boxes[(size_t)(b*NN+i)*4];
            float ax1=bx[0],ay1=bx[1],ax2=bx[2],ay2=bx[3];
            float cx=(ax1+ax2)*0.5f, cy=(ay1+ay2)*0.5f;
            int any=0;
            #pragma unroll 4
            for(int q=0;q<MM;q++){
                float qx1=sg[q][0],qy1=sg[q][1],qx2=sg[q][2],qy2=sg[q][3];
                bool igt=(cx>=qx1)&&(cx<=qx2)&&(cy>=qy1)&&(cy<=qy2);
                bool ict=(fabsf(cx-(qx1+qx2)*0.5f)<=CENTER_R)&&(fabsf(cy-(qy1+qy2)*0.5f)<=CENTER_R);
                any |= (igt||ict);
            }
            sval[i]=(unsigned char)any;
            g_valid[b*NN+i]=any;
            float x=logits[(size_t)(b*NN+i)*CC + cls_j];
            float p=sigm(x);
            float neg=-logf(1.f-p+EPSF)*0.75f*p*p;
            float pos=-logf(p+EPSF)*0.25f*(1.f-p)*(1.f-p);
            float cls_cost=2.f*(pos-neg);
            float na0=ax1/S_IMG,na1=ay1/S_IMG,na2=ax2/S_IMG,na3=ay2/S_IMG;
            float l1c=5.f*(fabsf(na0-ng0)+fabsf(na1-ng1)+fabsf(na2-ng2)+fabsf(na3-ng3));
            float ngiou=giou_pair(na0,na1,na2,na3,ng0,ng1,ng2,ng3);
            bool ingt=(cx>=gx1)&&(cx<=gx2)&&(cy>=gy1)&&(cy<=gy2);
            bool inct=(fabsf(cx-gcx)<=CENTER_R)&&(fabsf(cy-gcy)<=CENTER_R);
            float cost=cls_cost+l1c+2.f*(1.f-ngiou);
            cost += (ingt&&inct)?0.f:1e5f;
            cost += any?0.f:1e9f;
            col[i]=cost;
            g_costT[(size_t)(b*NN+i)*MM+j]=cost;
            float iou=iou_exact(ax1,ay1,ax2,ay2,gx1,gy1,gx2,gy2);
            float v=any? iou : 0.f;
            if(v>loc[9]){
                int k=9;
                #pragma unroll
                for(int q=9;q>0;q--){
                    if(loc[q-1]<v){ loc[q]=loc[q-1]; k=q-1; } else break;
                }
                loc[k]=v;
            }
        }
        // warp top-10 merge
        {
            int p=0; float out10[10];
            #pragma unroll
            for(int r=0;r<10;r++){
                float h=(p<10)?loc[p]:-1e30f;
                float m=h;
                #pragma unroll
                for(int off=16;off;off>>=1)
                    m=fmaxf(m,__shfl_xor_sync(0xffffffffu,m,off));
                out10[r]=m;
                unsigned ball=__ballot_sync(0xffffffffu, h==m);
                if(lane==(__ffs(ball)-1)) p++;
            }
            if(lane==0){
                #pragma unroll
                for(int r=0;r<10;r++) wtop[warp][r]=out10[r];
            }
        }
        __syncthreads();
        if(warp==0){
            int p=0; float s=0.f;
            #pragma unroll
            for(int r=0;r<10;r++){
                float h=(lane<8 && p<10)? wtop[lane][p] : -1e30f;
                float m=h;
                #pragma unroll
                for(int off=16;off;off>>=1)
                    m=fmaxf(m,__shfl_xor_sync(0xffffffffu,m,off));
                s+=m;
                unsigned ball=__ballot_sync(0xffffffffu, h==m && lane<8);
                if(lane==(__ffs(ball)-1)) p++;
            }
            if(lane==0){
                int dk=(int)s;
                if(dk<1)dk=1; if(dk>NN)dk=NN;
                s_dk=dk;
            }
        }
        __syncthreads();
        int dk=s_dk;
        #pragma unroll 2
        for(int i=tid;i<NN;i+=256){
            float myc=col[i];
            int r=0;
            #pragma unroll 4
            for(int k=0;k<NN;k++){
                float ck=col[k];
                r += (ck<myc) || (ck==myc && k<i);
            }
            g_matchT[(size_t)(b*NN+i)*MM+j]=(unsigned char)((r<dk) && sval[i]);
        }
        // ---- gcrop cache (per GT), fully unrolled for load batching ----
        {
            const float* gm=&gmask[(size_t)(b*MM+j)*(HM*HM)];
            float qx1=gx1*0.25f, qy1=gy1*0.25f, qx2=gx2*0.25f, qy2=gy2*0.25f;
            float gs=0.f;
            #pragma unroll
            for(int k=0;k<4;k++){
                int pix=tid+k*256;
                if(pix<TT*TT){
                    int ty=pix/TT, tx=pix%TT;
                    float ux=((float)tx+0.5f)/28.f, uy=((float)ty+0.5f)/28.f;
                    float Xg=qx1+(qx2-qx1)*ux-0.5f, Yg=qy1+(qy2-qy1)*uy-0.5f;
                    float gv=bilerp(gm,HM,HM,Xg,Yg);
                    g_gcrop[(size_t)(b*MM+j)*(TT*TT)+pix]=gv;
                    gs+=gv;
                }
            }
            #pragma unroll
            for(int off=16;off;off>>=1) gs+=__shfl_down_sync(0xffffffffu,gs,off);
            if(lane==0) sred[warp]=(double)gs;
            __syncthreads();
            if(tid==0){
                double t=0;
                #pragma unroll
                for(int w=0;w<8;w++) t+=sred[w];
                g_gsum[b*MM+j]=(float)t;
            }
        }
        return;
    }

    // ---- negative-class focal bulk ----
    {
        __shared__ double sred2[8];
        int base=(blk-PROJ_BLKS-COL_BLKS)*1280 + tid;
        double cl=0.0;
        #pragma unroll
        for(int k=0;k<5;k++){
            int e=base+k*256;
            float x=logits[e];
            float p=1.f/(1.f+__expf(-x));
            float sp=fmaxf(x,0.f)+log1pf(__expf(-fabsf(x)));
            cl += (double)(0.75f*p*p*sp);
        }
        #pragma unroll
        for(int off=16;off;off>>=1) cl+=__shfl_down_sync(0xffffffffu,cl,off);
        if(lane==0) sred2[warp]=cl;
        __syncthreads();
        if(tid==0){
            double a=0;
            #pragma unroll
            for(int w=0;w<8;w++) a+=sred2[w];
            atomicAdd(&g_accb[bank][0],a);
        }
    }
}

// ================= K2: 2 warps per proposal, fully-unrolled dice =================
__global__ void __launch_bounds__(256)
k_stage2(const float* __restrict__ logits, const float* __restrict__ boxes,
         const int* __restrict__ gcls, const float* __restrict__ gbox,
         float* __restrict__ out){
    int blk=blockIdx.x, tid=threadIdx.x;
    int lane=tid&31, warp=tid>>5;
    int bank=blk&31;
    int pw=warp>>1;                 // proposal slot within block (0..3)
    int half=warp&1;                // which half of pixels this warp covers
    int w = blk*4 + pw;             // proposal index (< 1200)
    __shared__ float sh_part[4][2][2];   // [slot][half][inter,sm]

    if(w < BB*NN && g_valid[w]){
        int b=w/NN;
        // inline assignment (both warps compute it; cheap, avoids sync)
        float c=(lane<MM)? __ldg(&g_costT[(size_t)w*MM+lane]) : 3.4e38f;
        unsigned char mb=(lane<MM)? g_matchT[(size_t)w*MM+lane] : 0;
        unsigned bits=__ballot_sync(0xffffffffu, lane<MM && mb);
        float bv=c; int bi=lane;
        #pragma unroll
        for(int off=16;off;off>>=1){
            float ov=__shfl_down_sync(0xffffffffu,bv,off);
            int   oi=__shfl_down_sync(0xffffffffu,bi,off);
            if(ov<bv || (ov==bv && oi<bi)){bv=ov;bi=oi;}
        }
        int best=__shfl_sync(0xffffffffu,bi,0);
        int cnt=__popc(bits);
        int j=(cnt==1)? (__ffs(bits)-1) : best;

        const float* pj=&g_proj[(size_t)(b*MM+j)*(HF*HF)];
        const float* gc=&g_gcrop[(size_t)(b*MM+j)*(TT*TT)];
        const float* bx=&boxes[(size_t)w*4];
        const float FS=(float)(64.0/896.0);
        float px1=bx[0]*FS, py1=bx[1]*FS, px2=bx[2]*FS, py2=bx[3]*FS;
        float inter=0.f, sm=0.f;
        // half 0: pixels 0..391, half 1: 392..783; each lane 13 unrolled slots
        int base=half*392+lane;
        #pragma unroll
        for(int k=0;k<13;k++){
            int pix=base+k*32;
            if(pix<(half+1)*392 && pix<TT*TT){
                int ty=pix/TT, tx=pix%TT;
                float ux=((float)tx+0.5f)/28.f, uy=((float)ty+0.5f)/28.f;
                float X=px1+(px2-px1)*ux-0.5f, Y=py1+(py2-py1)*uy-0.5f;
                float z=bilerp(pj,HF,HF,X,Y);
                float mv=1.f/(1.f+__expf(-z));
                float gv=__ldg(&gc[pix]);
                inter+=mv*gv; sm+=mv;
            }
        }
        #pragma unroll
        for(int off=16;off;off>>=1){
            inter+=__shfl_down_sync(0xffffffffu,inter,off);
            sm   +=__shfl_down_sync(0xffffffffu,sm,off);
        }
        if(lane==0){ sh_part[pw][half][0]=inter; sh_part[pw][half][1]=sm; }
    }
    __syncthreads();
    if(w < BB*NN && g_valid[w] && warp==(pw<<1) && lane==0){
        int b=w/NN;
        // recompute j quickly (scalar; 24 cached loads)
        float bv=3.4e38f; int bi=0, cnt=0, first=-1;
        #pragma unroll 4
        for(int q=0;q<MM;q++){
            float cq=__ldg(&g_costT[(size_t)w*MM+q]);
            if(cq<bv){bv=cq;bi=q;}
            int mbq=g_matchT[(size_t)w*MM+q];
            cnt+=mbq; if(mbq && first<0) first=q;
        }
        int j=(cnt==1)? first : bi;
        float inter=sh_part[pw][0][0]+sh_part[pw][1][0];
        float sm   =sh_part[pw][0][1]+sh_part[pw][1][1];
        float sgv=g_gsum[b*MM+j];
        double dice=(double)(1.f-2.f*inter/(sm+sgv+EPSF));
        const float* bx=&boxes[(size_t)w*4];
        const float* gb=&gbox[(size_t)(b*MM+j)*4];
        float na0=bx[0]/S_IMG,na1=bx[1]/S_IMG,na2=bx[2]/S_IMG,na3=bx[3]/S_IMG;
        float ng0=gb[0]/S_IMG,ng1=gb[1]/S_IMG,ng2=gb[2]/S_IMG,ng3=gb[3]/S_IMG;
        double l1=(double)(fabsf(na0-ng0)+fabsf(na1-ng1)+fabsf(na2-ng2)+fabsf(na3-ng3));
        double gl=(double)(1.f-giou_pair(na0,na1,na2,na3,ng0,ng1,ng2,ng3));
        int mcls=gcls[b*MM+j];
        float x=logits[(size_t)w*CC+mcls];
        float p=1.f/(1.f+expf(-x));
        float sp=fmaxf(x,0.f)+log1pf(expf(-fabsf(x)));
        float posv=0.25f*(1.f-p)*(1.f-p)*(sp-x);
        float negv=0.75f*p*p*sp;
        atomicAdd(&g_accb[bank][0],(double)(posv-negv));
        atomicAdd(&g_accb[bank][1],l1);
        atomicAdd(&g_accb[bank][2],gl);
        atomicAdd(&g_accb[bank][3],dice);
        atomicAdd(&g_accb[bank][4],1.0);
    }

    // ---- ticket: last finished block finalizes + resets ----
    __syncthreads();
    __threadfence();
    if(tid==0){
        int t=atomicAdd(&g_done,1);
        if(t==(int)gridDim.x-1){
            __threadfence();
            double a0=0,a1=0,a2=0,a3=0,a4=0;
            #pragma unroll
            for(int k=0;k<32;k++){
                a0+=g_accb[k][0]; a1+=g_accb[k][1]; a2+=g_accb[k][2];
                a3+=g_accb[k][3]; a4+=g_accb[k][4];
                g_accb[k][0]=0.0; g_accb[k][1]=0.0; g_accb[k][2]=0.0;
                g_accb[k][3]=0.0; g_accb[k][4]=0.0;
            }
            out[0]=(float)(2.0*a0/a4);
            out[1]=(float)(5.0*a1/a4);
            out[2]=(float)(2.0*a2/a4);
            out[3]=(float)(5.0*a3/a4);
            g_done=0;
        }
    }
}

extern "C" void kernel_launch(void* const* d_in, const int* in_sizes, int n_in,
                              void* d_out, int out_size){
    const float* logits=(const float*)d_in[0];
    const float* boxes =(const float*)d_in[1];
    const float* feat  =(const float*)d_in[2];
    const float* wmask =(const float*)d_in[3];
    const int*   gcls  =(const int*)  d_in[4];
    const float* gbox  =(const float*)d_in[5];
    const float* gmask =(const float*)d_in[6];
    float* out=(float*)d_out;

    k_stage1<<<K1_GRID,256>>>(logits,boxes,feat,wmask,gcls,gbox,gmask);
    k_stage2<<<K2_GRID,256>>>(logits,boxes,gcls,gbox,out);
}